// round 1
// baseline (speedup 1.0000x reference)
#include <cuda_runtime.h>

#define BATCH    8
#define CHANNELS 512
#define SPATIAL  1024   // 32*32
#define NHEADS   8
#define HDIM     64
#define GROUPS   8
#define GCH      64     // channels per group

// -------- scratch (static device globals: allocation-free) --------
__device__ float g_xn[BATCH*CHANNELS*SPATIAL];
__device__ float g_q [BATCH*CHANNELS*SPATIAL];
__device__ float g_k [BATCH*CHANNELS*SPATIAL];
__device__ float g_v [BATCH*CHANNELS*SPATIAL];
__device__ float g_ao[BATCH*CHANNELS*SPATIAL];

// ============================================================================
// GroupNorm: one block per (batch, group). 64 ch * 1024 spatial = 65536 elems.
// ============================================================================
__global__ __launch_bounds__(512) void gn_kernel(const float* __restrict__ x,
                                                 const float* __restrict__ w,
                                                 const float* __restrict__ bgn) {
    int bg = blockIdx.x;
    int b = bg >> 3, g = bg & 7;
    size_t base = (size_t)(b*CHANNELS + g*GCH) * SPATIAL;
    const float4* x4 = (const float4*)(x + base);
    float4* y4 = (float4*)(g_xn + base);
    int tid = threadIdx.x;

    float s = 0.f, ss = 0.f;
    for (int i = tid; i < GCH*SPATIAL/4; i += 512) {
        float4 v = x4[i];
        s  += v.x + v.y + v.z + v.w;
        ss += v.x*v.x + v.y*v.y + v.z*v.z + v.w*v.w;
    }
    __shared__ float rs[512], rq[512];
    rs[tid] = s; rq[tid] = ss;
    __syncthreads();
    for (int o = 256; o > 0; o >>= 1) {
        if (tid < o) { rs[tid] += rs[tid+o]; rq[tid] += rq[tid+o]; }
        __syncthreads();
    }
    float mu  = rs[0] * (1.f/65536.f);
    float var = rq[0] * (1.f/65536.f) - mu*mu;
    float rstd = rsqrtf(var + 1e-5f);

    for (int i = tid; i < GCH*SPATIAL/4; i += 512) {
        int c = g*GCH + (i >> 8);            // (i*4)/1024
        float wc = w[c], bc = bgn[c];
        float4 v = x4[i];
        float4 r;
        r.x = (v.x - mu) * rstd * wc + bc;
        r.y = (v.y - mu) * rstd * wc + bc;
        r.z = (v.z - mu) * rstd * wc + bc;
        r.w = (v.w - mu) * rstd * wc + bc;
        y4[i] = r;
    }
}

// ============================================================================
// Tiled SGEMM: Y[b][o][p] = sum_c W[o][c]*X[b][c][p] + bias[o] (+ resid)
// 64x64 tile, K-tile 16, 256 threads, 4x4 microtile (contiguous).
// src: 0 -> g_xn, 1 -> g_ao.   dst: 0..2 -> g_q/g_k/g_v, 3 -> Yext.
// ============================================================================
__global__ __launch_bounds__(256) void gemm_kernel(const float* __restrict__ W,
                                                   const float* __restrict__ bias,
                                                   const float* __restrict__ resid,
                                                   float* __restrict__ Yext,
                                                   int src, int dst) {
    __shared__ float As[16][68];   // [k][o], pad 68 (float4-aligned rows)
    __shared__ float Bs[16][64];   // [k][p]

    const float* X = (src == 0) ? g_xn : g_ao;
    float* Y = (dst == 0) ? g_q : (dst == 1) ? g_k : (dst == 2) ? g_v : Yext;

    int b = blockIdx.z;
    int oBase = blockIdx.y * 64;
    int pBase = blockIdx.x * 64;
    const float* Xb = X + (size_t)b * CHANNELS * SPATIAL;

    int tid = threadIdx.x;
    int tx = tid & 15, ty = tid >> 4;

    float acc[4][4] = {};

    for (int k0 = 0; k0 < CHANNELS; k0 += 16) {
        #pragma unroll
        for (int q = 0; q < 4; q++) {
            int i = tid + q*256;
            int kk = i & 15, oo = i >> 4;
            As[kk][oo] = W[(oBase + oo)*CHANNELS + k0 + kk];
        }
        {
            int kk = tid >> 4, pp = (tid & 15) << 2;
            *(float4*)&Bs[kk][pp] =
                *(const float4*)&Xb[(k0 + kk)*SPATIAL + pBase + pp];
        }
        __syncthreads();
        #pragma unroll
        for (int kk = 0; kk < 16; kk++) {
            float4 a  = *(float4*)&As[kk][ty << 2];
            float4 bv = *(float4*)&Bs[kk][tx << 2];
            acc[0][0] += a.x*bv.x; acc[0][1] += a.x*bv.y; acc[0][2] += a.x*bv.z; acc[0][3] += a.x*bv.w;
            acc[1][0] += a.y*bv.x; acc[1][1] += a.y*bv.y; acc[1][2] += a.y*bv.z; acc[1][3] += a.y*bv.w;
            acc[2][0] += a.z*bv.x; acc[2][1] += a.z*bv.y; acc[2][2] += a.z*bv.z; acc[2][3] += a.z*bv.w;
            acc[3][0] += a.w*bv.x; acc[3][1] += a.w*bv.y; acc[3][2] += a.w*bv.z; acc[3][3] += a.w*bv.w;
        }
        __syncthreads();
    }

    #pragma unroll
    for (int i = 0; i < 4; i++) {
        int o = oBase + (ty << 2) + i;
        float bi = bias[o];
        size_t off = (size_t)b*CHANNELS*SPATIAL + (size_t)o*SPATIAL + pBase + (tx << 2);
        float4 r = make_float4(acc[i][0]+bi, acc[i][1]+bi, acc[i][2]+bi, acc[i][3]+bi);
        if (resid) {
            float4 rv = *(const float4*)&resid[off];
            r.x += rv.x; r.y += rv.y; r.z += rv.z; r.w += rv.w;
        }
        *(float4*)&Y[off] = r;
    }
}

// ============================================================================
// Attention: one block per (b, h, 16-query tile). Full score row (1024) kept
// in shared; two compute phases + warp softmax.
// Shared: Qs[64][17] + S[16][1024] + KV union (Ks[64][132] / Vs[128][68])
// ============================================================================
#define ATTN_SMEM_FLOATS (64*17 + 16*1024 + 8704)

__global__ __launch_bounds__(256) void attn_kernel() {
    extern __shared__ float sm[];
    float* Qs = sm;                      // [64][17]  (d, n)
    float* S  = sm + 64*17;              // [16][1024]
    float* KV = S + 16*1024;             // 8704 floats

    int tid = threadIdx.x;
    int nBase = blockIdx.x * 16;
    int h = blockIdx.y, b = blockIdx.z;
    size_t base = ((size_t)b*CHANNELS + h*HDIM) * SPATIAL;
    const float* qp = g_q + base;
    const float* kp = g_k + base;
    const float* vp = g_v + base;

    // load Q tile (transposed: Qs[d][n])
    for (int i = tid; i < HDIM*16; i += 256) {
        int n = i & 15, d = i >> 4;
        Qs[d*17 + n] = qp[d*SPATIAL + nBase + n];
    }
    __syncthreads();

    // ---- phase 1: S[n][m] = scale * sum_d Q[d][n] K[d][m] ----
    int nt  = tid >> 5;             // 0..7 (2 rows each)
    int mt4 = (tid & 31) << 2;      // 0..124
    const float scale = 0.125f;     // HD^-0.5

    for (int m0 = 0; m0 < SPATIAL; m0 += 128) {
        for (int i = tid; i < HDIM*128; i += 256) {
            int m = i & 127, d = i >> 7;
            KV[d*132 + m] = kp[d*SPATIAL + m0 + m];   // Ks[d][m]
        }
        __syncthreads();
        float a0r[4] = {0,0,0,0}, a1r[4] = {0,0,0,0};
        #pragma unroll 8
        for (int d = 0; d < HDIM; d++) {
            float a0 = Qs[d*17 + nt*2];
            float a1 = Qs[d*17 + nt*2 + 1];
            float4 kv4 = *(float4*)&KV[d*132 + mt4];
            a0r[0] += a0*kv4.x; a0r[1] += a0*kv4.y; a0r[2] += a0*kv4.z; a0r[3] += a0*kv4.w;
            a1r[0] += a1*kv4.x; a1r[1] += a1*kv4.y; a1r[2] += a1*kv4.z; a1r[3] += a1*kv4.w;
        }
        *(float4*)&S[(nt*2)*SPATIAL + m0 + mt4] =
            make_float4(a0r[0]*scale, a0r[1]*scale, a0r[2]*scale, a0r[3]*scale);
        *(float4*)&S[(nt*2+1)*SPATIAL + m0 + mt4] =
            make_float4(a1r[0]*scale, a1r[1]*scale, a1r[2]*scale, a1r[3]*scale);
        __syncthreads();
    }

    // ---- softmax over each of 16 rows; warp w handles rows 2w, 2w+1 ----
    int warp = tid >> 5, lane = tid & 31;
    #pragma unroll
    for (int rr = 0; rr < 2; rr++) {
        float* Sr = S + (warp*2 + rr) * SPATIAL;
        float mx = -1e30f;
        for (int j = lane; j < SPATIAL; j += 32) mx = fmaxf(mx, Sr[j]);
        #pragma unroll
        for (int o = 16; o; o >>= 1) mx = fmaxf(mx, __shfl_xor_sync(0xffffffffu, mx, o));
        float sum = 0.f;
        for (int j = lane; j < SPATIAL; j += 32) {
            float e = __expf(Sr[j] - mx);
            Sr[j] = e; sum += e;
        }
        #pragma unroll
        for (int o = 16; o; o >>= 1) sum += __shfl_xor_sync(0xffffffffu, sum, o);
        float inv = 1.f / sum;
        for (int j = lane; j < SPATIAL; j += 32) Sr[j] *= inv;
    }
    __syncthreads();

    // ---- phase 2: O[n][d] = sum_m P[n][m] V[d][m] ----
    int n  = tid >> 4;              // 0..15
    int d4 = (tid & 15) << 2;       // 0..60
    float oacc[4] = {0,0,0,0};
    for (int m0 = 0; m0 < SPATIAL; m0 += 128) {
        for (int i = tid; i < 128*HDIM; i += 256) {
            int m = i & 127, d = i >> 7;
            KV[m*68 + d] = vp[d*SPATIAL + m0 + m];    // Vs[m][d]
        }
        __syncthreads();
        #pragma unroll 4
        for (int m = 0; m < 128; m++) {
            float p = S[n*SPATIAL + m0 + m];
            float4 v4 = *(float4*)&KV[m*68 + d4];
            oacc[0] += p*v4.x; oacc[1] += p*v4.y; oacc[2] += p*v4.z; oacc[3] += p*v4.w;
        }
        __syncthreads();
    }
    float* op = g_ao + base;
    #pragma unroll
    for (int j = 0; j < 4; j++)
        op[(d4 + j)*SPATIAL + nBase + n] = oacc[j];
}

// ============================================================================
extern "C" void kernel_launch(void* const* d_in, const int* in_sizes, int n_in,
                              void* d_out, int out_size) {
    const float* x  = (const float*)d_in[0];
    const float* nw = (const float*)d_in[1];
    const float* nb = (const float*)d_in[2];
    const float* qw = (const float*)d_in[3];
    const float* qb = (const float*)d_in[4];
    const float* kw = (const float*)d_in[5];
    const float* kb = (const float*)d_in[6];
    const float* vw = (const float*)d_in[7];
    const float* vb = (const float*)d_in[8];
    const float* pw = (const float*)d_in[9];
    const float* pb = (const float*)d_in[10];
    float* out = (float*)d_out;

    (void)in_sizes; (void)n_in; (void)out_size;

    static bool attr_set = false;
    if (!attr_set) {
        cudaFuncSetAttribute(attn_kernel,
                             cudaFuncAttributeMaxDynamicSharedMemorySize,
                             ATTN_SMEM_FLOATS * (int)sizeof(float));
        attr_set = true;
    }

    gn_kernel<<<BATCH*GROUPS, 512>>>(x, nw, nb);

    dim3 gg(SPATIAL/64, CHANNELS/64, BATCH);
    gemm_kernel<<<gg, 256>>>(qw, qb, nullptr, nullptr, 0, 0);
    gemm_kernel<<<gg, 256>>>(kw, kb, nullptr, nullptr, 0, 1);
    gemm_kernel<<<gg, 256>>>(vw, vb, nullptr, nullptr, 0, 2);

    attn_kernel<<<dim3(SPATIAL/16, NHEADS, BATCH), 256,
                  ATTN_SMEM_FLOATS * sizeof(float)>>>();

    gemm_kernel<<<gg, 256>>>(pw, pb, x, out, 1, 3);
}

// round 2
// speedup vs baseline: 1.2872x; 1.2872x over previous
#include <cuda_runtime.h>

#define BATCH    8
#define CHANNELS 512
#define SPATIAL  1024   // 32*32
#define NHEADS   8
#define HDIM     64
#define GROUPS   8
#define GCH      64
#define NBH      (BATCH*NHEADS)   // 64

// -------- scratch (static device globals: allocation-free) --------
__device__ float g_xn[BATCH*CHANNELS*SPATIAL];
__device__ float g_q [BATCH*CHANNELS*SPATIAL];
__device__ float g_k [BATCH*CHANNELS*SPATIAL];
__device__ float g_v [BATCH*CHANNELS*SPATIAL];
__device__ float g_ao[BATCH*CHANNELS*SPATIAL];
__device__ float g_s [(size_t)NBH*SPATIAL*SPATIAL];   // 268 MB attention scores
__device__ float g_mx[NBH*SPATIAL];
__device__ float g_inv[NBH*SPATIAL];

// ============================================================================
// GroupNorm: one block per (batch, group).
// ============================================================================
__global__ __launch_bounds__(512) void gn_kernel(const float* __restrict__ x,
                                                 const float* __restrict__ w,
                                                 const float* __restrict__ bgn) {
    int bg = blockIdx.x;
    int b = bg >> 3, g = bg & 7;
    size_t base = (size_t)(b*CHANNELS + g*GCH) * SPATIAL;
    const float4* x4 = (const float4*)(x + base);
    float4* y4 = (float4*)(g_xn + base);
    int tid = threadIdx.x;

    float s = 0.f, ss = 0.f;
    for (int i = tid; i < GCH*SPATIAL/4; i += 512) {
        float4 v = x4[i];
        s  += v.x + v.y + v.z + v.w;
        ss += v.x*v.x + v.y*v.y + v.z*v.z + v.w*v.w;
    }
    __shared__ float rs[512], rq[512];
    rs[tid] = s; rq[tid] = ss;
    __syncthreads();
    for (int o = 256; o > 0; o >>= 1) {
        if (tid < o) { rs[tid] += rs[tid+o]; rq[tid] += rq[tid+o]; }
        __syncthreads();
    }
    float mu  = rs[0] * (1.f/65536.f);
    float var = rq[0] * (1.f/65536.f) - mu*mu;
    float rstd = rsqrtf(var + 1e-5f);

    for (int i = tid; i < GCH*SPATIAL/4; i += 512) {
        int c = g*GCH + (i >> 8);
        float wc = w[c], bc = bgn[c];
        float4 v = x4[i];
        float4 r;
        r.x = (v.x - mu) * rstd * wc + bc;
        r.y = (v.y - mu) * rstd * wc + bc;
        r.z = (v.z - mu) * rstd * wc + bc;
        r.w = (v.w - mu) * rstd * wc + bc;
        y4[i] = r;
    }
}

// ============================================================================
// Conv1x1 GEMM: Y[b][o][p] = sum_c W[o][c]*X[b][c][p] + bias (+resid)
// 128x128 tile, Kt=16, 256 threads, 8x8 microtile.
// ============================================================================
__global__ __launch_bounds__(256, 2) void gemm128(const float* __restrict__ W,
                                                  const float* __restrict__ bias,
                                                  const float* __restrict__ resid,
                                                  float* __restrict__ Yext,
                                                  int src, int dst) {
    __shared__ float As[16][132];   // [k][o], padded
    __shared__ float Bs[16][128];   // [k][p]

    const float* X = (src == 0) ? g_xn : g_ao;
    float* Y = (dst == 0) ? g_q : (dst == 1) ? g_k : (dst == 2) ? g_v : Yext;

    int b = blockIdx.z;
    int oB = blockIdx.y * 128;
    int pB = blockIdx.x * 128;
    const float* Xb = X + (size_t)b * CHANNELS * SPATIAL;

    int tid = threadIdx.x;
    int tx = tid & 15, ty = tid >> 4;

    float acc[8][8] = {};

    for (int k0 = 0; k0 < CHANNELS; k0 += 16) {
        #pragma unroll
        for (int q = 0; q < 2; q++) {
            int i = tid + q*256;
            int row = i >> 2, c4 = (i & 3) << 2;
            float4 w4 = *(const float4*)&W[(size_t)(oB + row)*CHANNELS + k0 + c4];
            As[c4  ][row] = w4.x;
            As[c4+1][row] = w4.y;
            As[c4+2][row] = w4.z;
            As[c4+3][row] = w4.w;
            int kk = i >> 5, p4 = (i & 31) << 2;
            *(float4*)&Bs[kk][p4] =
                *(const float4*)&Xb[(size_t)(k0 + kk)*SPATIAL + pB + p4];
        }
        __syncthreads();
        #pragma unroll
        for (int kk = 0; kk < 16; kk++) {
            float a[8], bb[8];
            *(float4*)&a[0]  = *(float4*)&As[kk][ty*8];
            *(float4*)&a[4]  = *(float4*)&As[kk][ty*8 + 4];
            *(float4*)&bb[0] = *(float4*)&Bs[kk][tx*8];
            *(float4*)&bb[4] = *(float4*)&Bs[kk][tx*8 + 4];
            #pragma unroll
            for (int i = 0; i < 8; i++)
                #pragma unroll
                for (int j = 0; j < 8; j++)
                    acc[i][j] += a[i]*bb[j];
        }
        __syncthreads();
    }

    #pragma unroll
    for (int i = 0; i < 8; i++) {
        int o = oB + ty*8 + i;
        float bi = bias[o];
        size_t off = (size_t)b*CHANNELS*SPATIAL + (size_t)o*SPATIAL + pB + tx*8;
        float4 r0 = make_float4(acc[i][0]+bi, acc[i][1]+bi, acc[i][2]+bi, acc[i][3]+bi);
        float4 r1 = make_float4(acc[i][4]+bi, acc[i][5]+bi, acc[i][6]+bi, acc[i][7]+bi);
        if (resid) {
            float4 v0 = *(const float4*)&resid[off];
            float4 v1 = *(const float4*)&resid[off+4];
            r0.x += v0.x; r0.y += v0.y; r0.z += v0.z; r0.w += v0.w;
            r1.x += v1.x; r1.y += v1.y; r1.z += v1.z; r1.w += v1.w;
        }
        *(float4*)&Y[off]   = r0;
        *(float4*)&Y[off+4] = r1;
    }
}

// ============================================================================
// QK^T: S[bh][n][m] = scale * sum_d q[d][n]*k[d][m]
// Both operands d-major -> tiles load with zero transpose. 128x128x16 tiles.
// ============================================================================
__global__ __launch_bounds__(256, 2) void qk_kernel() {
    __shared__ float As[16][128];   // [d][n]
    __shared__ float Bs[16][128];   // [d][m]

    int bh = blockIdx.z;
    int nB = blockIdx.y * 128;
    int mB = blockIdx.x * 128;
    size_t base = ((size_t)(bh >> 3)*CHANNELS + (bh & 7)*HDIM) * SPATIAL;
    const float* qp = g_q + base;
    const float* kp = g_k + base;
    float* Sp = g_s + (size_t)bh * SPATIAL * SPATIAL;

    int tid = threadIdx.x;
    int tx = tid & 15, ty = tid >> 4;

    float acc[8][8] = {};

    for (int d0 = 0; d0 < HDIM; d0 += 16) {
        #pragma unroll
        for (int q = 0; q < 2; q++) {
            int i = tid + q*256;
            int d = i >> 5, c4 = (i & 31) << 2;
            *(float4*)&As[d][c4] = *(const float4*)&qp[(size_t)(d0+d)*SPATIAL + nB + c4];
            *(float4*)&Bs[d][c4] = *(const float4*)&kp[(size_t)(d0+d)*SPATIAL + mB + c4];
        }
        __syncthreads();
        #pragma unroll
        for (int kk = 0; kk < 16; kk++) {
            float a[8], bb[8];
            *(float4*)&a[0]  = *(float4*)&As[kk][ty*8];
            *(float4*)&a[4]  = *(float4*)&As[kk][ty*8 + 4];
            *(float4*)&bb[0] = *(float4*)&Bs[kk][tx*8];
            *(float4*)&bb[4] = *(float4*)&Bs[kk][tx*8 + 4];
            #pragma unroll
            for (int i = 0; i < 8; i++)
                #pragma unroll
                for (int j = 0; j < 8; j++)
                    acc[i][j] += a[i]*bb[j];
        }
        __syncthreads();
    }

    const float scale = 0.125f;   // HD^-0.5
    #pragma unroll
    for (int i = 0; i < 8; i++) {
        size_t off = (size_t)(nB + ty*8 + i)*SPATIAL + mB + tx*8;
        float4 r0 = make_float4(acc[i][0]*scale, acc[i][1]*scale, acc[i][2]*scale, acc[i][3]*scale);
        float4 r1 = make_float4(acc[i][4]*scale, acc[i][5]*scale, acc[i][6]*scale, acc[i][7]*scale);
        *(float4*)&Sp[off]   = r0;
        *(float4*)&Sp[off+4] = r1;
    }
}

// ============================================================================
// Softmax stats: per row, max and 1/sum(exp). One warp per row.
// ============================================================================
__global__ __launch_bounds__(256) void stats_kernel() {
    int row  = blockIdx.x*8 + (threadIdx.x >> 5);
    int lane = threadIdx.x & 31;
    const float* Sr = g_s + (size_t)row * SPATIAL;

    float4 v[8];
    #pragma unroll
    for (int j = 0; j < 8; j++)
        v[j] = *(const float4*)&Sr[j*128 + lane*4];

    float mx = -1e30f;
    #pragma unroll
    for (int j = 0; j < 8; j++) {
        mx = fmaxf(mx, fmaxf(fmaxf(v[j].x, v[j].y), fmaxf(v[j].z, v[j].w)));
    }
    #pragma unroll
    for (int o = 16; o; o >>= 1) mx = fmaxf(mx, __shfl_xor_sync(0xffffffffu, mx, o));

    float sum = 0.f;
    #pragma unroll
    for (int j = 0; j < 8; j++) {
        sum += __expf(v[j].x - mx) + __expf(v[j].y - mx)
             + __expf(v[j].z - mx) + __expf(v[j].w - mx);
    }
    #pragma unroll
    for (int o = 16; o; o >>= 1) sum += __shfl_xor_sync(0xffffffffu, sum, o);

    if (lane == 0) {
        g_mx[row]  = mx;
        g_inv[row] = 1.f / sum;
    }
}

// ============================================================================
// PV: O[bh][d][n] = sum_m V[d][m] * softmax(S)[n][m]
// Tile: 64d x 256n, K over m (16/step). exp applied while staging P.
// ============================================================================
__global__ __launch_bounds__(256, 2) void pv_kernel() {
    __shared__ float As[16][68];    // V^T tile: [m][d]
    __shared__ float Bs[16][260];   // P^T tile: [m][n]
    __shared__ float sMx[256], sInv[256];

    int nB = blockIdx.x * 256;
    int bh = blockIdx.y;
    size_t base = ((size_t)(bh >> 3)*CHANNELS + (bh & 7)*HDIM) * SPATIAL;
    const float* vp = g_v + base;
    const float* Sp = g_s + (size_t)bh * SPATIAL * SPATIAL;

    int tid = threadIdx.x;
    sMx[tid]  = g_mx [bh*SPATIAL + nB + tid];
    sInv[tid] = g_inv[bh*SPATIAL + nB + tid];

    int dy = (tid >> 5) * 8;   // 0..56
    int nx = (tid & 31) * 8;   // 0..248
    int dA  = tid >> 2;        // V load: d row
    int mA4 = (tid & 3) << 2;  // V load: m quad

    float acc[8][8] = {};
    __syncthreads();

    for (int m0 = 0; m0 < SPATIAL; m0 += 16) {
        // V tile [d64][m16] -> As[m][d]
        {
            float4 v4 = *(const float4*)&vp[(size_t)dA*SPATIAL + m0 + mA4];
            As[mA4  ][dA] = v4.x;
            As[mA4+1][dA] = v4.y;
            As[mA4+2][dA] = v4.z;
            As[mA4+3][dA] = v4.w;
        }
        // P tile [n256][m16] -> exp -> Bs[m][n]
        #pragma unroll
        for (int q = 0; q < 4; q++) {
            int i = tid + q*256;
            int n = i >> 2, m4 = (i & 3) << 2;
            float4 s4 = *(const float4*)&Sp[(size_t)(nB + n)*SPATIAL + m0 + m4];
            float mxv = sMx[n], invv = sInv[n];
            Bs[m4  ][n] = __expf(s4.x - mxv) * invv;
            Bs[m4+1][n] = __expf(s4.y - mxv) * invv;
            Bs[m4+2][n] = __expf(s4.z - mxv) * invv;
            Bs[m4+3][n] = __expf(s4.w - mxv) * invv;
        }
        __syncthreads();
        #pragma unroll
        for (int m = 0; m < 16; m++) {
            float a[8], bb[8];
            *(float4*)&a[0]  = *(float4*)&As[m][dy];
            *(float4*)&a[4]  = *(float4*)&As[m][dy + 4];
            *(float4*)&bb[0] = *(float4*)&Bs[m][nx];
            *(float4*)&bb[4] = *(float4*)&Bs[m][nx + 4];
            #pragma unroll
            for (int i = 0; i < 8; i++)
                #pragma unroll
                for (int j = 0; j < 8; j++)
                    acc[i][j] += a[i]*bb[j];
        }
        __syncthreads();
    }

    float* op = g_ao + base;
    #pragma unroll
    for (int i = 0; i < 8; i++) {
        size_t off = (size_t)(dy + i)*SPATIAL + nB + nx;
        *(float4*)&op[off]   = *(float4*)&acc[i][0];
        *(float4*)&op[off+4] = *(float4*)&acc[i][4];
    }
}

// ============================================================================
extern "C" void kernel_launch(void* const* d_in, const int* in_sizes, int n_in,
                              void* d_out, int out_size) {
    const float* x  = (const float*)d_in[0];
    const float* nw = (const float*)d_in[1];
    const float* nb = (const float*)d_in[2];
    const float* qw = (const float*)d_in[3];
    const float* qb = (const float*)d_in[4];
    const float* kw = (const float*)d_in[5];
    const float* kb = (const float*)d_in[6];
    const float* vw = (const float*)d_in[7];
    const float* vb = (const float*)d_in[8];
    const float* pw = (const float*)d_in[9];
    const float* pb = (const float*)d_in[10];
    float* out = (float*)d_out;
    (void)in_sizes; (void)n_in; (void)out_size;

    gn_kernel<<<BATCH*GROUPS, 512>>>(x, nw, nb);

    dim3 gg(SPATIAL/128, CHANNELS/128, BATCH);
    gemm128<<<gg, 256>>>(qw, qb, nullptr, nullptr, 0, 0);
    gemm128<<<gg, 256>>>(kw, kb, nullptr, nullptr, 0, 1);
    gemm128<<<gg, 256>>>(vw, vb, nullptr, nullptr, 0, 2);

    qk_kernel<<<dim3(SPATIAL/128, SPATIAL/128, NBH), 256>>>();
    stats_kernel<<<NBH*SPATIAL/8, 256>>>();
    pv_kernel<<<dim3(SPATIAL/256, NBH), 256>>>();

    gemm128<<<gg, 256>>>(pw, pb, x, out, 1, 3);
}

// round 5
// speedup vs baseline: 3.4672x; 2.6936x over previous
#include <cuda_runtime.h>
#include <cstdint>

#define BATCH    8
#define CHANNELS 512
#define SPATIAL  1024
#define NHEADS   8
#define HDIM     64
#define GCH      64
#define NBH      (BATCH*NHEADS)
#define BC       (CHANNELS*SPATIAL)

// -------- scratch --------
__device__ float g_xn [BATCH*BC];     // [b][c][p]
__device__ float g_q  [BATCH*BC];
__device__ float g_k  [BATCH*BC];
__device__ float g_v  [BATCH*BC];
__device__ float g_ao [BATCH*BC];     // [b][c][p]
__device__ float g_s  [(size_t)NBH*SPATIAL*SPATIAL];
__device__ float g_mx [NBH*SPATIAL];
__device__ float g_inv[NBH*SPATIAL];

// ---------------- mma helpers ----------------
__device__ __forceinline__ float tf32r(float x) {
    uint32_t u;
    asm("cvt.rna.tf32.f32 %0, %1;" : "=r"(u) : "f"(x));
    return __uint_as_float(u);
}
__device__ __forceinline__ void mma8(float* c, const uint32_t* a, const uint32_t* b) {
    asm volatile("mma.sync.aligned.m16n8k8.row.col.f32.tf32.tf32.f32 "
        "{%0,%1,%2,%3}, {%4,%5,%6,%7}, {%8,%9}, {%0,%1,%2,%3};"
        : "+f"(c[0]), "+f"(c[1]), "+f"(c[2]), "+f"(c[3])
        : "r"(a[0]), "r"(a[1]), "r"(a[2]), "r"(a[3]), "r"(b[0]), "r"(b[1]));
}

// ============================================================================
// GroupNorm
// ============================================================================
__global__ __launch_bounds__(512) void gn_kernel(const float* __restrict__ x,
                                                 const float* __restrict__ w,
                                                 const float* __restrict__ bgn) {
    int bg = blockIdx.x;
    int b = bg >> 3, g = bg & 7;
    size_t base = (size_t)(b*CHANNELS + g*GCH) * SPATIAL;
    const float4* x4 = (const float4*)(x + base);
    float4* y4 = (float4*)(g_xn + base);
    int tid = threadIdx.x;

    float s = 0.f, ss = 0.f;
    for (int i = tid; i < GCH*SPATIAL/4; i += 512) {
        float4 v = x4[i];
        s  += v.x + v.y + v.z + v.w;
        ss += v.x*v.x + v.y*v.y + v.z*v.z + v.w*v.w;
    }
    __shared__ float rs[512], rq[512];
    rs[tid] = s; rq[tid] = ss;
    __syncthreads();
    for (int o = 256; o > 0; o >>= 1) {
        if (tid < o) { rs[tid] += rs[tid+o]; rq[tid] += rq[tid+o]; }
        __syncthreads();
    }
    float mu  = rs[0] * (1.f/65536.f);
    float var = rq[0] * (1.f/65536.f) - mu*mu;
    float rstd = rsqrtf(var + 1e-5f);

    for (int i = tid; i < GCH*SPATIAL/4; i += 512) {
        int c = g*GCH + (i >> 8);
        float wc = w[c], bc = bgn[c];
        float4 v = x4[i];
        float4 r;
        r.x = (v.x - mu) * rstd * wc + bc;
        r.y = (v.y - mu) * rstd * wc + bc;
        r.z = (v.z - mu) * rstd * wc + bc;
        r.w = (v.w - mu) * rstd * wc + bc;
        y4[i] = r;
    }
}

// ============================================================================
// Conv1x1 via tf32 mma: Y[o][p] = W[o][:]·X[:][p] + bias (+resid)
// Block tile 128(o) x 128(p), Kt=16. 8 warps: wy=wid&3 (o/32), wx=wid>>2 (p/64)
// ============================================================================
__device__ __forceinline__ void conv_core(const float* __restrict__ W,
                                          const float* __restrict__ bias,
                                          const float* __restrict__ X,
                                          const float* __restrict__ resid,
                                          float* __restrict__ Y) {
    __shared__ float As[16][132];   // [k][o]
    __shared__ float Bs[16][132];   // [k][p]
    int tid = threadIdx.x, lane = tid & 31, wid = tid >> 5;
    int wy = wid & 3, wx = wid >> 2;
    int lq = lane >> 2, lr = lane & 3;

    float acc[2][8][4];
    #pragma unroll
    for (int i = 0; i < 2; i++)
        #pragma unroll
        for (int j = 0; j < 8; j++)
            #pragma unroll
            for (int t = 0; t < 4; t++) acc[i][j][t] = 0.f;

    for (int k0 = 0; k0 < CHANNELS; k0 += 16) {
        #pragma unroll
        for (int q = 0; q < 2; q++) {
            int i = tid + q*256;
            int row = i >> 2, c4 = (i & 3) << 2;
            float4 w4 = *(const float4*)&W[(size_t)row*CHANNELS + k0 + c4];
            As[c4  ][row] = tf32r(w4.x);
            As[c4+1][row] = tf32r(w4.y);
            As[c4+2][row] = tf32r(w4.z);
            As[c4+3][row] = tf32r(w4.w);
            int kk = i >> 5, p4 = (i & 31) << 2;
            float4 x4 = *(const float4*)&X[(size_t)(k0 + kk)*SPATIAL + p4];
            float4 xt = make_float4(tf32r(x4.x), tf32r(x4.y), tf32r(x4.z), tf32r(x4.w));
            *(float4*)&Bs[kk][p4] = xt;
        }
        __syncthreads();
        #pragma unroll
        for (int s = 0; s < 2; s++) {
            int kb = s*8 + lr;
            uint32_t a[2][4], b[8][2];
            #pragma unroll
            for (int mi = 0; mi < 2; mi++) {
                int o = wy*32 + mi*16 + lq;
                a[mi][0] = __float_as_uint(As[kb  ][o]);
                a[mi][1] = __float_as_uint(As[kb  ][o+8]);
                a[mi][2] = __float_as_uint(As[kb+4][o]);
                a[mi][3] = __float_as_uint(As[kb+4][o+8]);
            }
            #pragma unroll
            for (int ni = 0; ni < 8; ni++) {
                int p = wx*64 + ni*8 + lq;
                b[ni][0] = __float_as_uint(Bs[kb  ][p]);
                b[ni][1] = __float_as_uint(Bs[kb+4][p]);
            }
            #pragma unroll
            for (int mi = 0; mi < 2; mi++)
                #pragma unroll
                for (int ni = 0; ni < 8; ni++)
                    mma8(acc[mi][ni], a[mi], b[ni]);
        }
        __syncthreads();
    }

    #pragma unroll
    for (int mi = 0; mi < 2; mi++) {
        int o0 = wy*32 + mi*16 + lq;
        float bi0 = bias[o0], bi8 = bias[o0+8];
        #pragma unroll
        for (int ni = 0; ni < 8; ni++) {
            int p = wx*64 + ni*8 + lr*2;
            size_t off0 = (size_t)o0*SPATIAL + p;
            size_t off8 = (size_t)(o0+8)*SPATIAL + p;
            float2 r0 = make_float2(acc[mi][ni][0] + bi0, acc[mi][ni][1] + bi0);
            float2 r8 = make_float2(acc[mi][ni][2] + bi8, acc[mi][ni][3] + bi8);
            if (resid) {
                float2 v0 = *(const float2*)&resid[off0];
                float2 v8 = *(const float2*)&resid[off8];
                r0.x += v0.x; r0.y += v0.y;
                r8.x += v8.x; r8.y += v8.y;
            }
            *(float2*)&Y[off0] = r0;
            *(float2*)&Y[off8] = r8;
        }
    }
}

__global__ __launch_bounds__(256) void mma_qkv(const float* __restrict__ qw, const float* __restrict__ qb,
                                               const float* __restrict__ kw, const float* __restrict__ kb,
                                               const float* __restrict__ vw, const float* __restrict__ vb) {
    int b = blockIdx.z;
    int sel = blockIdx.y >> 2;
    int oB = (blockIdx.y & 3) * 128;
    int pB = blockIdx.x * 128;
    const float* W  = sel == 0 ? qw : sel == 1 ? kw : vw;
    const float* bi = sel == 0 ? qb : sel == 1 ? kb : vb;
    float* Y        = sel == 0 ? g_q : sel == 1 ? g_k : g_v;
    conv_core(W + (size_t)oB*CHANNELS, bi + oB,
              g_xn + (size_t)b*BC + pB, nullptr,
              Y + (size_t)b*BC + (size_t)oB*SPATIAL + pB);
}

__global__ __launch_bounds__(256) void mma_proj(const float* __restrict__ pw, const float* __restrict__ pb,
                                                const float* __restrict__ x, float* __restrict__ out) {
    int b = blockIdx.z;
    int oB = blockIdx.y * 128;
    int pB = blockIdx.x * 128;
    size_t bb = (size_t)b*BC;
    conv_core(pw + (size_t)oB*CHANNELS, pb + oB,
              g_ao + bb + pB,
              x + bb + (size_t)oB*SPATIAL + pB,
              out + bb + (size_t)oB*SPATIAL + pB);
}

// ============================================================================
// QK^T via mma: S[n][m] = scale * sum_d Q[d][n]*K[d][m]. Tile 128x128, Kt=16.
// ============================================================================
__global__ __launch_bounds__(256) void qk_kernel() {
    __shared__ float As[16][132];   // [d][n]
    __shared__ float Bs[16][132];   // [d][m]

    int bh = blockIdx.z;
    int nB = blockIdx.y * 128;
    int mB = blockIdx.x * 128;
    size_t base = ((size_t)(bh >> 3)*CHANNELS + (bh & 7)*HDIM) * SPATIAL;
    const float* qp = g_q + base;
    const float* kp = g_k + base;
    float* Sp = g_s + (size_t)bh * SPATIAL * SPATIAL;

    int tid = threadIdx.x, lane = tid & 31, wid = tid >> 5;
    int wy = wid & 3, wx = wid >> 2;
    int lq = lane >> 2, lr = lane & 3;

    float acc[2][8][4];
    #pragma unroll
    for (int i = 0; i < 2; i++)
        #pragma unroll
        for (int j = 0; j < 8; j++)
            #pragma unroll
            for (int t = 0; t < 4; t++) acc[i][j][t] = 0.f;

    for (int d0 = 0; d0 < HDIM; d0 += 16) {
        #pragma unroll
        for (int q = 0; q < 2; q++) {
            int i = tid + q*256;
            int d = i >> 5, c4 = (i & 31) << 2;
            float4 q4 = *(const float4*)&qp[(size_t)(d0+d)*SPATIAL + nB + c4];
            float4 k4 = *(const float4*)&kp[(size_t)(d0+d)*SPATIAL + mB + c4];
            *(float4*)&As[d][c4] = make_float4(tf32r(q4.x), tf32r(q4.y), tf32r(q4.z), tf32r(q4.w));
            *(float4*)&Bs[d][c4] = make_float4(tf32r(k4.x), tf32r(k4.y), tf32r(k4.z), tf32r(k4.w));
        }
        __syncthreads();
        #pragma unroll
        for (int s = 0; s < 2; s++) {
            int kb = s*8 + lr;
            uint32_t a[2][4], b[8][2];
            #pragma unroll
            for (int mi = 0; mi < 2; mi++) {
                int n = wy*32 + mi*16 + lq;
                a[mi][0] = __float_as_uint(As[kb  ][n]);
                a[mi][1] = __float_as_uint(As[kb  ][n+8]);
                a[mi][2] = __float_as_uint(As[kb+4][n]);
                a[mi][3] = __float_as_uint(As[kb+4][n+8]);
            }
            #pragma unroll
            for (int ni = 0; ni < 8; ni++) {
                int m = wx*64 + ni*8 + lq;
                b[ni][0] = __float_as_uint(Bs[kb  ][m]);
                b[ni][1] = __float_as_uint(Bs[kb+4][m]);
            }
            #pragma unroll
            for (int mi = 0; mi < 2; mi++)
                #pragma unroll
                for (int ni = 0; ni < 8; ni++)
                    mma8(acc[mi][ni], a[mi], b[ni]);
        }
        __syncthreads();
    }

    const float scale = 0.125f;
    #pragma unroll
    for (int mi = 0; mi < 2; mi++) {
        int n0 = nB + wy*32 + mi*16 + lq;
        #pragma unroll
        for (int ni = 0; ni < 8; ni++) {
            int m = mB + wx*64 + ni*8 + lr*2;
            *(float2*)&Sp[(size_t)n0*SPATIAL + m] =
                make_float2(acc[mi][ni][0]*scale, acc[mi][ni][1]*scale);
            *(float2*)&Sp[(size_t)(n0+8)*SPATIAL + m] =
                make_float2(acc[mi][ni][2]*scale, acc[mi][ni][3]*scale);
        }
    }
}

// ============================================================================
// Softmax stats
// ============================================================================
__global__ __launch_bounds__(256) void stats_kernel() {
    int row  = blockIdx.x*8 + (threadIdx.x >> 5);
    int lane = threadIdx.x & 31;
    const float* Sr = g_s + (size_t)row * SPATIAL;

    float4 v[8];
    #pragma unroll
    for (int j = 0; j < 8; j++)
        v[j] = *(const float4*)&Sr[j*128 + lane*4];

    float mx = -1e30f;
    #pragma unroll
    for (int j = 0; j < 8; j++)
        mx = fmaxf(mx, fmaxf(fmaxf(v[j].x, v[j].y), fmaxf(v[j].z, v[j].w)));
    #pragma unroll
    for (int o = 16; o; o >>= 1) mx = fmaxf(mx, __shfl_xor_sync(0xffffffffu, mx, o));

    float sum = 0.f;
    #pragma unroll
    for (int j = 0; j < 8; j++)
        sum += __expf(v[j].x - mx) + __expf(v[j].y - mx)
             + __expf(v[j].z - mx) + __expf(v[j].w - mx);
    #pragma unroll
    for (int o = 16; o; o >>= 1) sum += __shfl_xor_sync(0xffffffffu, sum, o);

    if (lane == 0) { g_mx[row] = mx; g_inv[row] = 1.f / sum; }
}

// ============================================================================
// PV via mma: O[d][n] = sum_m V[d][m] * P[n][m]. Tile 64(d) x 256(n), Kt=16.
// 8 warps: wy=wid&1 (d/32), wx=wid>>1 (n/64).
// ============================================================================
__global__ __launch_bounds__(256) void pv_kernel() {
    __shared__ float As[16][68];    // [m][d]
    __shared__ float Bs[16][260];   // [m][n] (exp applied)
    __shared__ float sMx[256], sInv[256];

    int nB = blockIdx.x * 256;
    int bh = blockIdx.y;
    size_t base = ((size_t)(bh >> 3)*CHANNELS + (bh & 7)*HDIM) * SPATIAL;
    const float* vp = g_v + base;
    const float* Sp = g_s + (size_t)bh * SPATIAL * SPATIAL;

    int tid = threadIdx.x, lane = tid & 31, wid = tid >> 5;
    int wy = wid & 1, wx = wid >> 1;
    int lq = lane >> 2, lr = lane & 3;

    sMx[tid]  = g_mx [bh*SPATIAL + nB + tid];
    sInv[tid] = g_inv[bh*SPATIAL + nB + tid];

    float acc[2][8][4];
    #pragma unroll
    for (int i = 0; i < 2; i++)
        #pragma unroll
        for (int j = 0; j < 8; j++)
            #pragma unroll
            for (int t = 0; t < 4; t++) acc[i][j][t] = 0.f;
    __syncthreads();

    for (int m0 = 0; m0 < SPATIAL; m0 += 16) {
        {
            int dA = tid >> 2, mA4 = (tid & 3) << 2;
            float4 v4 = *(const float4*)&vp[(size_t)dA*SPATIAL + m0 + mA4];
            As[mA4  ][dA] = tf32r(v4.x);
            As[mA4+1][dA] = tf32r(v4.y);
            As[mA4+2][dA] = tf32r(v4.z);
            As[mA4+3][dA] = tf32r(v4.w);
        }
        #pragma unroll
        for (int q = 0; q < 4; q++) {
            int i = tid + q*256;
            int n = i >> 2, m4 = (i & 3) << 2;
            float4 s4 = *(const float4*)&Sp[(size_t)(nB + n)*SPATIAL + m0 + m4];
            float mxv = sMx[n], invv = sInv[n];
            Bs[m4  ][n] = tf32r(__expf(s4.x - mxv) * invv);
            Bs[m4+1][n] = tf32r(__expf(s4.y - mxv) * invv);
            Bs[m4+2][n] = tf32r(__expf(s4.z - mxv) * invv);
            Bs[m4+3][n] = tf32r(__expf(s4.w - mxv) * invv);
        }
        __syncthreads();
        #pragma unroll
        for (int s = 0; s < 2; s++) {
            int kb = s*8 + lr;
            uint32_t a[2][4], b[8][2];
            #pragma unroll
            for (int mi = 0; mi < 2; mi++) {
                int d = wy*32 + mi*16 + lq;
                a[mi][0] = __float_as_uint(As[kb  ][d]);
                a[mi][1] = __float_as_uint(As[kb  ][d+8]);
                a[mi][2] = __float_as_uint(As[kb+4][d]);
                a[mi][3] = __float_as_uint(As[kb+4][d+8]);
            }
            #pragma unroll
            for (int ni = 0; ni < 8; ni++) {
                int n = wx*64 + ni*8 + lq;
                b[ni][0] = __float_as_uint(Bs[kb  ][n]);
                b[ni][1] = __float_as_uint(Bs[kb+4][n]);
            }
            #pragma unroll
            for (int mi = 0; mi < 2; mi++)
                #pragma unroll
                for (int ni = 0; ni < 8; ni++)
                    mma8(acc[mi][ni], a[mi], b[ni]);
        }
        __syncthreads();
    }

    float* op = g_ao + base;
    #pragma unroll
    for (int mi = 0; mi < 2; mi++) {
        int d0 = wy*32 + mi*16 + lq;
        #pragma unroll
        for (int ni = 0; ni < 8; ni++) {
            int n = nB + wx*64 + ni*8 + lr*2;
            *(float2*)&op[(size_t)d0*SPATIAL + n] =
                make_float2(acc[mi][ni][0], acc[mi][ni][1]);
            *(float2*)&op[(size_t)(d0+8)*SPATIAL + n] =
                make_float2(acc[mi][ni][2], acc[mi][ni][3]);
        }
    }
}

// ============================================================================
extern "C" void kernel_launch(void* const* d_in, const int* in_sizes, int n_in,
                              void* d_out, int out_size) {
    const float* x  = (const float*)d_in[0];
    const float* nw = (const float*)d_in[1];
    const float* nb = (const float*)d_in[2];
    const float* qw = (const float*)d_in[3];
    const float* qb = (const float*)d_in[4];
    const float* kw = (const float*)d_in[5];
    const float* kb = (const float*)d_in[6];
    const float* vw = (const float*)d_in[7];
    const float* vb = (const float*)d_in[8];
    const float* pw = (const float*)d_in[9];
    const float* pb = (const float*)d_in[10];
    float* out = (float*)d_out;
    (void)in_sizes; (void)n_in; (void)out_size;

    gn_kernel<<<BATCH*8, 512>>>(x, nw, nb);

    mma_qkv<<<dim3(SPATIAL/128, 12, BATCH), 256>>>(qw, qb, kw, kb, vw, vb);

    qk_kernel<<<dim3(SPATIAL/128, SPATIAL/128, NBH), 256>>>();
    stats_kernel<<<NBH*SPATIAL/8, 256>>>();
    pv_kernel<<<dim3(SPATIAL/256, NBH), 256>>>();

    mma_proj<<<dim3(SPATIAL/128, CHANNELS/128, BATCH), 256>>>(pw, pb, x, out);
}

// round 6
// speedup vs baseline: 4.2734x; 1.2325x over previous
#include <cuda_runtime.h>
#include <cstdint>

#define BATCH    8
#define CHANNELS 512
#define SPATIAL  1024
#define NHEADS   8
#define HDIM     64
#define GCH      64
#define NBH      (BATCH*NHEADS)
#define BC       (CHANNELS*SPATIAL)

// -------- scratch --------
__device__ float g_xn [BATCH*BC];     // [b][c][p]
__device__ float g_q  [BATCH*BC];
__device__ float g_k  [BATCH*BC];
__device__ float g_v  [BATCH*BC];
__device__ float g_ao [BATCH*BC];     // [b][c][p]

// ---------------- mma helpers ----------------
__device__ __forceinline__ float tf32r(float x) {
    uint32_t u;
    asm("cvt.rna.tf32.f32 %0, %1;" : "=r"(u) : "f"(x));
    return __uint_as_float(u);
}
__device__ __forceinline__ void mma8(float* c, const uint32_t* a, const uint32_t* b) {
    asm volatile("mma.sync.aligned.m16n8k8.row.col.f32.tf32.tf32.f32 "
        "{%0,%1,%2,%3}, {%4,%5,%6,%7}, {%8,%9}, {%0,%1,%2,%3};"
        : "+f"(c[0]), "+f"(c[1]), "+f"(c[2]), "+f"(c[3])
        : "r"(a[0]), "r"(a[1]), "r"(a[2]), "r"(a[3]), "r"(b[0]), "r"(b[1]));
}

// ============================================================================
// GroupNorm
// ============================================================================
__global__ __launch_bounds__(512) void gn_kernel(const float* __restrict__ x,
                                                 const float* __restrict__ w,
                                                 const float* __restrict__ bgn) {
    int bg = blockIdx.x;
    int b = bg >> 3, g = bg & 7;
    size_t base = (size_t)(b*CHANNELS + g*GCH) * SPATIAL;
    const float4* x4 = (const float4*)(x + base);
    float4* y4 = (float4*)(g_xn + base);
    int tid = threadIdx.x;

    float s = 0.f, ss = 0.f;
    for (int i = tid; i < GCH*SPATIAL/4; i += 512) {
        float4 v = x4[i];
        s  += v.x + v.y + v.z + v.w;
        ss += v.x*v.x + v.y*v.y + v.z*v.z + v.w*v.w;
    }
    __shared__ float rs[512], rq[512];
    rs[tid] = s; rq[tid] = ss;
    __syncthreads();
    for (int o = 256; o > 0; o >>= 1) {
        if (tid < o) { rs[tid] += rs[tid+o]; rq[tid] += rq[tid+o]; }
        __syncthreads();
    }
    float mu  = rs[0] * (1.f/65536.f);
    float var = rq[0] * (1.f/65536.f) - mu*mu;
    float rstd = rsqrtf(var + 1e-5f);

    for (int i = tid; i < GCH*SPATIAL/4; i += 512) {
        int c = g*GCH + (i >> 8);
        float wc = w[c], bc = bgn[c];
        float4 v = x4[i];
        float4 r;
        r.x = (v.x - mu) * rstd * wc + bc;
        r.y = (v.y - mu) * rstd * wc + bc;
        r.z = (v.z - mu) * rstd * wc + bc;
        r.w = (v.w - mu) * rstd * wc + bc;
        y4[i] = r;
    }
}

// ============================================================================
// Conv1x1 via tf32 mma (unchanged from R5)
// ============================================================================
__device__ __forceinline__ void conv_core(const float* __restrict__ W,
                                          const float* __restrict__ bias,
                                          const float* __restrict__ X,
                                          const float* __restrict__ resid,
                                          float* __restrict__ Y) {
    __shared__ float As[16][132];
    __shared__ float Bs[16][132];
    int tid = threadIdx.x, lane = tid & 31, wid = tid >> 5;
    int wy = wid & 3, wx = wid >> 2;
    int lq = lane >> 2, lr = lane & 3;

    float acc[2][8][4];
    #pragma unroll
    for (int i = 0; i < 2; i++)
        #pragma unroll
        for (int j = 0; j < 8; j++)
            #pragma unroll
            for (int t = 0; t < 4; t++) acc[i][j][t] = 0.f;

    for (int k0 = 0; k0 < CHANNELS; k0 += 16) {
        #pragma unroll
        for (int q = 0; q < 2; q++) {
            int i = tid + q*256;
            int row = i >> 2, c4 = (i & 3) << 2;
            float4 w4 = *(const float4*)&W[(size_t)row*CHANNELS + k0 + c4];
            As[c4  ][row] = tf32r(w4.x);
            As[c4+1][row] = tf32r(w4.y);
            As[c4+2][row] = tf32r(w4.z);
            As[c4+3][row] = tf32r(w4.w);
            int kk = i >> 5, p4 = (i & 31) << 2;
            float4 x4 = *(const float4*)&X[(size_t)(k0 + kk)*SPATIAL + p4];
            *(float4*)&Bs[kk][p4] =
                make_float4(tf32r(x4.x), tf32r(x4.y), tf32r(x4.z), tf32r(x4.w));
        }
        __syncthreads();
        #pragma unroll
        for (int s = 0; s < 2; s++) {
            int kb = s*8 + lr;
            uint32_t a[2][4], b[8][2];
            #pragma unroll
            for (int mi = 0; mi < 2; mi++) {
                int o = wy*32 + mi*16 + lq;
                a[mi][0] = __float_as_uint(As[kb  ][o]);
                a[mi][1] = __float_as_uint(As[kb  ][o+8]);
                a[mi][2] = __float_as_uint(As[kb+4][o]);
                a[mi][3] = __float_as_uint(As[kb+4][o+8]);
            }
            #pragma unroll
            for (int ni = 0; ni < 8; ni++) {
                int p = wx*64 + ni*8 + lq;
                b[ni][0] = __float_as_uint(Bs[kb  ][p]);
                b[ni][1] = __float_as_uint(Bs[kb+4][p]);
            }
            #pragma unroll
            for (int mi = 0; mi < 2; mi++)
                #pragma unroll
                for (int ni = 0; ni < 8; ni++)
                    mma8(acc[mi][ni], a[mi], b[ni]);
        }
        __syncthreads();
    }

    #pragma unroll
    for (int mi = 0; mi < 2; mi++) {
        int o0 = wy*32 + mi*16 + lq;
        float bi0 = bias[o0], bi8 = bias[o0+8];
        #pragma unroll
        for (int ni = 0; ni < 8; ni++) {
            int p = wx*64 + ni*8 + lr*2;
            size_t off0 = (size_t)o0*SPATIAL + p;
            size_t off8 = (size_t)(o0+8)*SPATIAL + p;
            float2 r0 = make_float2(acc[mi][ni][0] + bi0, acc[mi][ni][1] + bi0);
            float2 r8 = make_float2(acc[mi][ni][2] + bi8, acc[mi][ni][3] + bi8);
            if (resid) {
                float2 v0 = *(const float2*)&resid[off0];
                float2 v8 = *(const float2*)&resid[off8];
                r0.x += v0.x; r0.y += v0.y;
                r8.x += v8.x; r8.y += v8.y;
            }
            *(float2*)&Y[off0] = r0;
            *(float2*)&Y[off8] = r8;
        }
    }
}

__global__ __launch_bounds__(256) void mma_qkv(const float* __restrict__ qw, const float* __restrict__ qb,
                                               const float* __restrict__ kw, const float* __restrict__ kb,
                                               const float* __restrict__ vw, const float* __restrict__ vb) {
    int b = blockIdx.z;
    int sel = blockIdx.y >> 2;
    int oB = (blockIdx.y & 3) * 128;
    int pB = blockIdx.x * 128;
    const float* W  = sel == 0 ? qw : sel == 1 ? kw : vw;
    const float* bi = sel == 0 ? qb : sel == 1 ? kb : vb;
    float* Y        = sel == 0 ? g_q : sel == 1 ? g_k : g_v;
    conv_core(W + (size_t)oB*CHANNELS, bi + oB,
              g_xn + (size_t)b*BC + pB, nullptr,
              Y + (size_t)b*BC + (size_t)oB*SPATIAL + pB);
}

__global__ __launch_bounds__(256) void mma_proj(const float* __restrict__ pw, const float* __restrict__ pb,
                                                const float* __restrict__ x, float* __restrict__ out) {
    int b = blockIdx.z;
    int oB = blockIdx.y * 128;
    int pB = blockIdx.x * 128;
    size_t bb = (size_t)b*BC;
    conv_core(pw + (size_t)oB*CHANNELS, pb + oB,
              g_ao + bb + pB,
              x + bb + (size_t)oB*SPATIAL + pB,
              out + bb + (size_t)oB*SPATIAL + pB);
}

// ============================================================================
// Flash attention: one CTA per (bh, 128-query tile). 8 warps, warp w owns
// query rows w*16..w*16+15. Loop over 8 K/V tiles of 128 with online softmax.
// S never leaves registers/SMEM.
// Dyn smem: Qs[64][132] | union(Ks[64][132], Ps[128][132], Os[128][65]) | Vs[128][68]
// ============================================================================
#define QS_OFF  0
#define KS_OFF  (64*132)            // 8448
#define VS_OFF  (KS_OFF + 128*132)  // 8448 + 16896 = 25344
#define FL_SMEM ((VS_OFF + 128*68) * sizeof(float))   // 136192 B

__global__ __launch_bounds__(256) void flash_kernel() {
    extern __shared__ float sm[];
    float* Qs = sm + QS_OFF;    // [d][n]  scale folded
    float* Ks = sm + KS_OFF;    // [d][m]
    float* Ps = sm + KS_OFF;    // [m][n]  (union with Ks)
    float* Os = sm + KS_OFF;    // [n][65] (union)
    float* Vs = sm + VS_OFF;    // [m][d]

    int nB = blockIdx.x * 128;
    int bh = blockIdx.y;
    size_t base = ((size_t)(bh >> 3)*CHANNELS + (bh & 7)*HDIM) * SPATIAL;
    const float* qp = g_q + base;
    const float* kp = g_k + base;
    const float* vp = g_v + base;

    int tid = threadIdx.x, lane = tid & 31, wid = tid >> 5;
    int lq = lane >> 2, lr = lane & 3;
    int n0 = wid * 16;

    // stage Q once, scale folded (S = (Q*scale)^T K)
    #pragma unroll
    for (int q = 0; q < 8; q++) {
        int i = tid + q*256;
        int d = i >> 5, m4 = (i & 31) << 2;
        float4 v = *(const float4*)&qp[(size_t)d*SPATIAL + nB + m4];
        Qs[d*132 + m4    ] = tf32r(v.x * 0.125f);
        Qs[d*132 + m4 + 1] = tf32r(v.y * 0.125f);
        Qs[d*132 + m4 + 2] = tf32r(v.z * 0.125f);
        Qs[d*132 + m4 + 3] = tf32r(v.w * 0.125f);
    }

    float accO[8][4];
    #pragma unroll
    for (int i = 0; i < 8; i++)
        #pragma unroll
        for (int t = 0; t < 4; t++) accO[i][t] = 0.f;
    float mPrev0 = -1e30f, mPrev8 = -1e30f;
    float l0 = 0.f, l8 = 0.f;

    for (int m0 = 0; m0 < SPATIAL; m0 += 128) {
        // ---- stage K [d][m] and V [m][d] ----
        __syncthreads();   // Ps/Os (prev iter) fully consumed
        #pragma unroll
        for (int q = 0; q < 8; q++) {
            int i = tid + q*256;
            int d = i >> 5, m4 = (i & 31) << 2;
            float4 v = *(const float4*)&kp[(size_t)d*SPATIAL + m0 + m4];
            Ks[d*132 + m4    ] = tf32r(v.x);
            Ks[d*132 + m4 + 1] = tf32r(v.y);
            Ks[d*132 + m4 + 2] = tf32r(v.z);
            Ks[d*132 + m4 + 3] = tf32r(v.w);
        }
        {
            int dA = tid >> 2;
            #pragma unroll
            for (int q = 0; q < 8; q++) {
                int mA4 = ((tid & 3) << 2) + q*16;
                float4 v = *(const float4*)&vp[(size_t)dA*SPATIAL + m0 + mA4];
                Vs[(mA4  )*68 + dA] = tf32r(v.x);
                Vs[(mA4+1)*68 + dA] = tf32r(v.y);
                Vs[(mA4+2)*68 + dA] = tf32r(v.z);
                Vs[(mA4+3)*68 + dA] = tf32r(v.w);
            }
        }
        __syncthreads();

        // ---- S = Q^T K  (warp rows n0..n0+15, all 128 m) ----
        float accS[16][4];
        #pragma unroll
        for (int i = 0; i < 16; i++)
            #pragma unroll
            for (int t = 0; t < 4; t++) accS[i][t] = 0.f;
        #pragma unroll
        for (int s = 0; s < 8; s++) {
            int kb = s*8 + lr;
            uint32_t a[4];
            a[0] = __float_as_uint(Qs[kb*132 + nB % 1 + n0 + lq]);      // nB%1==0
            a[1] = __float_as_uint(Qs[kb*132 + n0 + lq + 8]);
            a[2] = __float_as_uint(Qs[(kb+4)*132 + n0 + lq]);
            a[3] = __float_as_uint(Qs[(kb+4)*132 + n0 + lq + 8]);
            #pragma unroll
            for (int ni = 0; ni < 16; ni++) {
                uint32_t b[2];
                b[0] = __float_as_uint(Ks[kb*132 + ni*8 + lq]);
                b[1] = __float_as_uint(Ks[(kb+4)*132 + ni*8 + lq]);
                mma8(accS[ni], a, b);
            }
        }
        __syncthreads();   // all warps done reading Ks before Ps overwrite

        // ---- online softmax (rows r0=n0+lq, r8=n0+lq+8) ----
        float tm0 = -1e30f, tm8 = -1e30f;
        #pragma unroll
        for (int ni = 0; ni < 16; ni++) {
            tm0 = fmaxf(tm0, fmaxf(accS[ni][0], accS[ni][1]));
            tm8 = fmaxf(tm8, fmaxf(accS[ni][2], accS[ni][3]));
        }
        tm0 = fmaxf(tm0, __shfl_xor_sync(0xffffffffu, tm0, 1));
        tm0 = fmaxf(tm0, __shfl_xor_sync(0xffffffffu, tm0, 2));
        tm8 = fmaxf(tm8, __shfl_xor_sync(0xffffffffu, tm8, 1));
        tm8 = fmaxf(tm8, __shfl_xor_sync(0xffffffffu, tm8, 2));

        float mNew0 = fmaxf(mPrev0, tm0);
        float mNew8 = fmaxf(mPrev8, tm8);
        float alpha0 = __expf(mPrev0 - mNew0);
        float alpha8 = __expf(mPrev8 - mNew8);
        mPrev0 = mNew0; mPrev8 = mNew8;

        float sum0 = 0.f, sum8 = 0.f;
        #pragma unroll
        for (int ni = 0; ni < 16; ni++) {
            float p0 = __expf(accS[ni][0] - mNew0);
            float p1 = __expf(accS[ni][1] - mNew0);
            float p2 = __expf(accS[ni][2] - mNew8);
            float p3 = __expf(accS[ni][3] - mNew8);
            sum0 += p0 + p1; sum8 += p2 + p3;
            int m = ni*8 + lr*2;
            Ps[(m  )*132 + n0 + lq    ] = p0;
            Ps[(m+1)*132 + n0 + lq    ] = p1;
            Ps[(m  )*132 + n0 + lq + 8] = p2;
            Ps[(m+1)*132 + n0 + lq + 8] = p3;
        }
        sum0 += __shfl_xor_sync(0xffffffffu, sum0, 1);
        sum0 += __shfl_xor_sync(0xffffffffu, sum0, 2);
        sum8 += __shfl_xor_sync(0xffffffffu, sum8, 1);
        sum8 += __shfl_xor_sync(0xffffffffu, sum8, 2);
        l0 = l0*alpha0 + sum0;
        l8 = l8*alpha8 + sum8;

        #pragma unroll
        for (int ni = 0; ni < 8; ni++) {
            accO[ni][0] *= alpha0; accO[ni][1] *= alpha0;
            accO[ni][2] *= alpha8; accO[ni][3] *= alpha8;
        }
        __syncthreads();

        // ---- O += P V ----
        #pragma unroll
        for (int s = 0; s < 16; s++) {
            int kb = s*8 + lr;
            uint32_t a[4];
            a[0] = __float_as_uint(Ps[kb*132 + n0 + lq]);
            a[1] = __float_as_uint(Ps[kb*132 + n0 + lq + 8]);
            a[2] = __float_as_uint(Ps[(kb+4)*132 + n0 + lq]);
            a[3] = __float_as_uint(Ps[(kb+4)*132 + n0 + lq + 8]);
            #pragma unroll
            for (int ni = 0; ni < 8; ni++) {
                uint32_t b[2];
                b[0] = __float_as_uint(Vs[kb*68 + ni*8 + lq]);
                b[1] = __float_as_uint(Vs[(kb+4)*68 + ni*8 + lq]);
                mma8(accO[ni], a, b);
            }
        }
    }

    // ---- finalize: O /= l, via smem transpose to [d][n] ----
    float inv0 = 1.f / l0, inv8 = 1.f / l8;
    __syncthreads();   // Ps reads done; reuse as Os[n][65]
    #pragma unroll
    for (int ni = 0; ni < 8; ni++) {
        int d = ni*8 + lr*2;
        Os[(n0 + lq    )*65 + d    ] = accO[ni][0]*inv0;
        Os[(n0 + lq    )*65 + d + 1] = accO[ni][1]*inv0;
        Os[(n0 + lq + 8)*65 + d    ] = accO[ni][2]*inv8;
        Os[(n0 + lq + 8)*65 + d + 1] = accO[ni][3]*inv8;
    }
    __syncthreads();
    float* op = g_ao + base;
    #pragma unroll
    for (int q = 0; q < 32; q++) {
        int i = tid + q*256;
        int d = i >> 7, n = i & 127;
        op[(size_t)d*SPATIAL + nB + n] = Os[n*65 + d];
    }
}

// ============================================================================
extern "C" void kernel_launch(void* const* d_in, const int* in_sizes, int n_in,
                              void* d_out, int out_size) {
    const float* x  = (const float*)d_in[0];
    const float* nw = (const float*)d_in[1];
    const float* nb = (const float*)d_in[2];
    const float* qw = (const float*)d_in[3];
    const float* qb = (const float*)d_in[4];
    const float* kw = (const float*)d_in[5];
    const float* kb = (const float*)d_in[6];
    const float* vw = (const float*)d_in[7];
    const float* vb = (const float*)d_in[8];
    const float* pw = (const float*)d_in[9];
    const float* pb = (const float*)d_in[10];
    float* out = (float*)d_out;
    (void)in_sizes; (void)n_in; (void)out_size;

    cudaFuncSetAttribute(flash_kernel,
                         cudaFuncAttributeMaxDynamicSharedMemorySize,
                         (int)FL_SMEM);

    gn_kernel<<<BATCH*8, 512>>>(x, nw, nb);

    mma_qkv<<<dim3(SPATIAL/128, 12, BATCH), 256>>>(qw, qb, kw, kb, vw, vb);

    flash_kernel<<<dim3(SPATIAL/128, NBH), 256, FL_SMEM>>>();

    mma_proj<<<dim3(SPATIAL/128, CHANNELS/128, BATCH), 256>>>(pw, pb, x, out);
}

// round 7
// speedup vs baseline: 6.3638x; 1.4892x over previous
#include <cuda_runtime.h>
#include <cstdint>

#define BATCH    8
#define CHANNELS 512
#define SPATIAL  1024
#define NHEADS   8
#define HDIM     64
#define GCH      64
#define NBH      (BATCH*NHEADS)
#define BC       (CHANNELS*SPATIAL)

// -------- scratch --------
__device__ float g_xn [BATCH*BC];     // [b][c][p]
__device__ float g_q  [BATCH*BC];
__device__ float g_k  [BATCH*BC];
__device__ float g_v  [BATCH*BC];
__device__ float g_ao [BATCH*BC];     // [b][c][p]

// ---------------- helpers ----------------
__device__ __forceinline__ float tf32r(float x) {
    uint32_t u;
    asm("cvt.rna.tf32.f32 %0, %1;" : "=r"(u) : "f"(x));
    return __uint_as_float(u);
}
__device__ __forceinline__ void mma8(float* c, const uint32_t* a, const uint32_t* b) {
    asm volatile("mma.sync.aligned.m16n8k8.row.col.f32.tf32.tf32.f32 "
        "{%0,%1,%2,%3}, {%4,%5,%6,%7}, {%8,%9}, {%0,%1,%2,%3};"
        : "+f"(c[0]), "+f"(c[1]), "+f"(c[2]), "+f"(c[3])
        : "r"(a[0]), "r"(a[1]), "r"(a[2]), "r"(a[3]), "r"(b[0]), "r"(b[1]));
}
__device__ __forceinline__ void cp16(float* s, const float* g) {
    uint32_t sa = (uint32_t)__cvta_generic_to_shared(s);
    asm volatile("cp.async.cg.shared.global [%0], [%1], 16;" :: "r"(sa), "l"(g));
}
#define CP_COMMIT() asm volatile("cp.async.commit_group;" ::: "memory")
#define CP_WAIT(N)  asm volatile("cp.async.wait_group %0;" :: "n"(N) : "memory")

// ============================================================================
// GroupNorm
// ============================================================================
__global__ __launch_bounds__(512) void gn_kernel(const float* __restrict__ x,
                                                 const float* __restrict__ w,
                                                 const float* __restrict__ bgn) {
    int bg = blockIdx.x;
    int b = bg >> 3, g = bg & 7;
    size_t base = (size_t)(b*CHANNELS + g*GCH) * SPATIAL;
    const float4* x4 = (const float4*)(x + base);
    float4* y4 = (float4*)(g_xn + base);
    int tid = threadIdx.x;

    float s = 0.f, ss = 0.f;
    for (int i = tid; i < GCH*SPATIAL/4; i += 512) {
        float4 v = x4[i];
        s  += v.x + v.y + v.z + v.w;
        ss += v.x*v.x + v.y*v.y + v.z*v.z + v.w*v.w;
    }
    __shared__ float rs[512], rq[512];
    rs[tid] = s; rq[tid] = ss;
    __syncthreads();
    for (int o = 256; o > 0; o >>= 1) {
        if (tid < o) { rs[tid] += rs[tid+o]; rq[tid] += rq[tid+o]; }
        __syncthreads();
    }
    float mu  = rs[0] * (1.f/65536.f);
    float var = rq[0] * (1.f/65536.f) - mu*mu;
    float rstd = rsqrtf(var + 1e-5f);

    for (int i = tid; i < GCH*SPATIAL/4; i += 512) {
        int c = g*GCH + (i >> 8);
        float wc = w[c], bc = bgn[c];
        float4 v = x4[i];
        float4 r;
        r.x = (v.x - mu) * rstd * wc + bc;
        r.y = (v.y - mu) * rstd * wc + bc;
        r.z = (v.z - mu) * rstd * wc + bc;
        r.w = (v.w - mu) * rstd * wc + bc;
        y4[i] = r;
    }
}

// ============================================================================
// Conv1x1 via tf32 mma + double-buffered cp.async.
// Tile 128(o) x 128(p), Kt=32. As[o][36] row-major-K, Bs[k][136].
// ============================================================================
#define CAS_STR 36
#define CBS_STR 136
#define CAS_SZ  (128*CAS_STR)            // 4608
#define CBS_SZ  (32*CBS_STR)             // 4352
#define CONV_SMEM ((2*CAS_SZ + 2*CBS_SZ) * sizeof(float))   // 71680 B

__device__ __forceinline__ void conv_stage(float* As, float* Bs,
                                           const float* W, const float* X,
                                           int k0, int tid) {
    #pragma unroll
    for (int q = 0; q < 4; q++) {
        int i = tid + q*256;
        int row = i >> 3, c4 = (i & 7) << 2;
        cp16(&As[row*CAS_STR + c4], &W[(size_t)row*CHANNELS + k0 + c4]);
    }
    #pragma unroll
    for (int q = 0; q < 4; q++) {
        int i = tid + q*256;
        int kk = i >> 5, p4 = (i & 31) << 2;
        cp16(&Bs[kk*CBS_STR + p4], &X[(size_t)(k0 + kk)*SPATIAL + p4]);
    }
}

__device__ __forceinline__ void conv_core(const float* __restrict__ W,
                                          const float* __restrict__ bias,
                                          const float* __restrict__ X,
                                          const float* __restrict__ resid,
                                          float* __restrict__ Y) {
    extern __shared__ float csm[];
    float* As[2] = { csm, csm + CAS_SZ };
    float* Bs[2] = { csm + 2*CAS_SZ, csm + 2*CAS_SZ + CBS_SZ };

    int tid = threadIdx.x, lane = tid & 31, wid = tid >> 5;
    int wy = wid & 3, wx = wid >> 2;
    int lq = lane >> 2, lr = lane & 3;

    float acc[2][8][4];
    #pragma unroll
    for (int i = 0; i < 2; i++)
        #pragma unroll
        for (int j = 0; j < 8; j++)
            #pragma unroll
            for (int t = 0; t < 4; t++) acc[i][j][t] = 0.f;

    conv_stage(As[0], Bs[0], W, X, 0, tid);
    CP_COMMIT();

    for (int it = 0; it < CHANNELS/32; it++) {
        int cur = it & 1;
        if (it + 1 < CHANNELS/32) {
            conv_stage(As[cur^1], Bs[cur^1], W, X, (it+1)*32, tid);
            CP_COMMIT();
            CP_WAIT(1);
        } else {
            CP_WAIT(0);
        }
        __syncthreads();

        const float* A = As[cur];
        const float* B = Bs[cur];
        #pragma unroll
        for (int s = 0; s < 4; s++) {
            int kb = s*8 + lr;
            uint32_t a[2][4], b[8][2];
            #pragma unroll
            for (int mi = 0; mi < 2; mi++) {
                int o = wy*32 + mi*16 + lq;
                a[mi][0] = __float_as_uint(A[(o  )*CAS_STR + kb]);
                a[mi][1] = __float_as_uint(A[(o+8)*CAS_STR + kb]);
                a[mi][2] = __float_as_uint(A[(o  )*CAS_STR + kb+4]);
                a[mi][3] = __float_as_uint(A[(o+8)*CAS_STR + kb+4]);
            }
            #pragma unroll
            for (int ni = 0; ni < 8; ni++) {
                int p = wx*64 + ni*8 + lq;
                b[ni][0] = __float_as_uint(B[(kb  )*CBS_STR + p]);
                b[ni][1] = __float_as_uint(B[(kb+4)*CBS_STR + p]);
            }
            #pragma unroll
            for (int mi = 0; mi < 2; mi++)
                #pragma unroll
                for (int ni = 0; ni < 8; ni++)
                    mma8(acc[mi][ni], a[mi], b[ni]);
        }
        __syncthreads();
    }

    #pragma unroll
    for (int mi = 0; mi < 2; mi++) {
        int o0 = wy*32 + mi*16 + lq;
        float bi0 = bias[o0], bi8 = bias[o0+8];
        #pragma unroll
        for (int ni = 0; ni < 8; ni++) {
            int p = wx*64 + ni*8 + lr*2;
            size_t off0 = (size_t)o0*SPATIAL + p;
            size_t off8 = (size_t)(o0+8)*SPATIAL + p;
            float2 r0 = make_float2(acc[mi][ni][0] + bi0, acc[mi][ni][1] + bi0);
            float2 r8 = make_float2(acc[mi][ni][2] + bi8, acc[mi][ni][3] + bi8);
            if (resid) {
                float2 v0 = *(const float2*)&resid[off0];
                float2 v8 = *(const float2*)&resid[off8];
                r0.x += v0.x; r0.y += v0.y;
                r8.x += v8.x; r8.y += v8.y;
            }
            *(float2*)&Y[off0] = r0;
            *(float2*)&Y[off8] = r8;
        }
    }
}

__global__ __launch_bounds__(256, 2) void mma_qkv(const float* __restrict__ qw, const float* __restrict__ qb,
                                                  const float* __restrict__ kw, const float* __restrict__ kb,
                                                  const float* __restrict__ vw, const float* __restrict__ vb) {
    int b = blockIdx.z;
    int sel = blockIdx.y >> 2;
    int oB = (blockIdx.y & 3) * 128;
    int pB = blockIdx.x * 128;
    const float* W  = sel == 0 ? qw : sel == 1 ? kw : vw;
    const float* bi = sel == 0 ? qb : sel == 1 ? kb : vb;
    float* Y        = sel == 0 ? g_q : sel == 1 ? g_k : g_v;
    conv_core(W + (size_t)oB*CHANNELS, bi + oB,
              g_xn + (size_t)b*BC + pB, nullptr,
              Y + (size_t)b*BC + (size_t)oB*SPATIAL + pB);
}

__global__ __launch_bounds__(256, 2) void mma_proj(const float* __restrict__ pw, const float* __restrict__ pb,
                                                   const float* __restrict__ x, float* __restrict__ out) {
    int b = blockIdx.z;
    int oB = blockIdx.y * 128;
    int pB = blockIdx.x * 128;
    size_t bb = (size_t)b*BC;
    conv_core(pw + (size_t)oB*CHANNELS, pb + oB,
              g_ao + bb + pB,
              x + bb + (size_t)oB*SPATIAL + pB,
              out + bb + (size_t)oB*SPATIAL + pB);
}

// ============================================================================
// Flash attention v2: CTA per (bh, 128-query tile), m-tile 64, 2 CTAs/SM.
// Qs[64][136] | union(Ks[64][72], Ps[64][136], Os[128][65]) | Vs[64][68] (natural [d][m])
// ============================================================================
#define QSTR 136
#define KSTR 72
#define PSTR 136
#define VSTR 68
#define FQ_OFF 0
#define FK_OFF (64*QSTR)                 // 8704
#define FV_OFF (FK_OFF + 64*PSTR)        // 8704 + 8704 = 17408
#define FL_SMEM ((FV_OFF + 64*VSTR) * sizeof(float))   // (17408+4352)*4 = 87040 B

__global__ __launch_bounds__(256, 2) void flash_kernel() {
    extern __shared__ float sm[];
    float* Qs = sm + FQ_OFF;    // [d][n]
    float* Ks = sm + FK_OFF;    // [d][m]
    float* Ps = sm + FK_OFF;    // [m][n] (union)
    float* Os = sm + FK_OFF;    // [n][65] (union)
    float* Vs = sm + FV_OFF;    // [d][m] natural

    int nB = blockIdx.x * 128;
    int bh = blockIdx.y;
    size_t base = ((size_t)(bh >> 3)*CHANNELS + (bh & 7)*HDIM) * SPATIAL;
    const float* qp = g_q + base;
    const float* kp = g_k + base;
    const float* vp = g_v + base;

    int tid = threadIdx.x, lane = tid & 31, wid = tid >> 5;
    int lq = lane >> 2, lr = lane & 3;
    int n0 = wid * 16;

    // stage Q once, scale folded
    #pragma unroll
    for (int q = 0; q < 8; q++) {
        int i = tid + q*256;
        int d = i >> 5, n4 = (i & 31) << 2;
        float4 v = *(const float4*)&qp[(size_t)d*SPATIAL + nB + n4];
        Qs[d*QSTR + n4    ] = tf32r(v.x * 0.125f);
        Qs[d*QSTR + n4 + 1] = tf32r(v.y * 0.125f);
        Qs[d*QSTR + n4 + 2] = tf32r(v.z * 0.125f);
        Qs[d*QSTR + n4 + 3] = tf32r(v.w * 0.125f);
    }

    float accO[8][4];
    #pragma unroll
    for (int i = 0; i < 8; i++)
        #pragma unroll
        for (int t = 0; t < 4; t++) accO[i][t] = 0.f;
    float mPrev0 = -1e30f, mPrev8 = -1e30f;
    float l0 = 0.f, l8 = 0.f;

    for (int m0 = 0; m0 < SPATIAL; m0 += 64) {
        __syncthreads();   // prev Ps/Vs reads done; Qs writes visible (1st iter)
        // stage K [d][m] and V [d][m] via cp.async (contiguous rows)
        #pragma unroll
        for (int q = 0; q < 4; q++) {
            int i = tid + q*256;
            int d = i >> 4, m4 = (i & 15) << 2;
            cp16(&Ks[d*KSTR + m4], &kp[(size_t)d*SPATIAL + m0 + m4]);
        }
        #pragma unroll
        for (int q = 0; q < 4; q++) {
            int i = tid + q*256;
            int d = i >> 4, m4 = (i & 15) << 2;
            cp16(&Vs[d*VSTR + m4], &vp[(size_t)d*SPATIAL + m0 + m4]);
        }
        CP_COMMIT();
        CP_WAIT(0);
        __syncthreads();

        // ---- S = Q^T K : warp rows n0..n0+15 x 64 keys ----
        float accS[8][4];
        #pragma unroll
        for (int i = 0; i < 8; i++)
            #pragma unroll
            for (int t = 0; t < 4; t++) accS[i][t] = 0.f;
        #pragma unroll
        for (int s = 0; s < 8; s++) {
            int kb = s*8 + lr;
            uint32_t a[4];
            a[0] = __float_as_uint(Qs[kb*QSTR + n0 + lq]);
            a[1] = __float_as_uint(Qs[kb*QSTR + n0 + lq + 8]);
            a[2] = __float_as_uint(Qs[(kb+4)*QSTR + n0 + lq]);
            a[3] = __float_as_uint(Qs[(kb+4)*QSTR + n0 + lq + 8]);
            #pragma unroll
            for (int ni = 0; ni < 8; ni++) {
                uint32_t b[2];
                b[0] = __float_as_uint(Ks[kb*KSTR + ni*8 + lq]);
                b[1] = __float_as_uint(Ks[(kb+4)*KSTR + ni*8 + lq]);
                mma8(accS[ni], a, b);
            }
        }
        __syncthreads();   // Ks reads done before Ps overwrite

        // ---- online softmax (rows n0+lq, n0+lq+8) ----
        float tm0 = -1e30f, tm8 = -1e30f;
        #pragma unroll
        for (int ni = 0; ni < 8; ni++) {
            tm0 = fmaxf(tm0, fmaxf(accS[ni][0], accS[ni][1]));
            tm8 = fmaxf(tm8, fmaxf(accS[ni][2], accS[ni][3]));
        }
        tm0 = fmaxf(tm0, __shfl_xor_sync(0xffffffffu, tm0, 1));
        tm0 = fmaxf(tm0, __shfl_xor_sync(0xffffffffu, tm0, 2));
        tm8 = fmaxf(tm8, __shfl_xor_sync(0xffffffffu, tm8, 1));
        tm8 = fmaxf(tm8, __shfl_xor_sync(0xffffffffu, tm8, 2));

        float mNew0 = fmaxf(mPrev0, tm0);
        float mNew8 = fmaxf(mPrev8, tm8);
        float alpha0 = __expf(mPrev0 - mNew0);
        float alpha8 = __expf(mPrev8 - mNew8);
        mPrev0 = mNew0; mPrev8 = mNew8;

        float sum0 = 0.f, sum8 = 0.f;
        #pragma unroll
        for (int ni = 0; ni < 8; ni++) {
            float p0 = __expf(accS[ni][0] - mNew0);
            float p1 = __expf(accS[ni][1] - mNew0);
            float p2 = __expf(accS[ni][2] - mNew8);
            float p3 = __expf(accS[ni][3] - mNew8);
            sum0 += p0 + p1; sum8 += p2 + p3;
            int m = ni*8 + lr*2;
            Ps[(m  )*PSTR + n0 + lq    ] = p0;
            Ps[(m+1)*PSTR + n0 + lq    ] = p1;
            Ps[(m  )*PSTR + n0 + lq + 8] = p2;
            Ps[(m+1)*PSTR + n0 + lq + 8] = p3;
        }
        sum0 += __shfl_xor_sync(0xffffffffu, sum0, 1);
        sum0 += __shfl_xor_sync(0xffffffffu, sum0, 2);
        sum8 += __shfl_xor_sync(0xffffffffu, sum8, 1);
        sum8 += __shfl_xor_sync(0xffffffffu, sum8, 2);
        l0 = l0*alpha0 + sum0;
        l8 = l8*alpha8 + sum8;

        #pragma unroll
        for (int ni = 0; ni < 8; ni++) {
            accO[ni][0] *= alpha0; accO[ni][1] *= alpha0;
            accO[ni][2] *= alpha8; accO[ni][3] *= alpha8;
        }
        __syncthreads();

        // ---- O += P V^T ----
        #pragma unroll
        for (int s = 0; s < 8; s++) {
            int kb = s*8 + lr;
            uint32_t a[4];
            a[0] = __float_as_uint(Ps[kb*PSTR + n0 + lq]);
            a[1] = __float_as_uint(Ps[kb*PSTR + n0 + lq + 8]);
            a[2] = __float_as_uint(Ps[(kb+4)*PSTR + n0 + lq]);
            a[3] = __float_as_uint(Ps[(kb+4)*PSTR + n0 + lq + 8]);
            #pragma unroll
            for (int ni = 0; ni < 8; ni++) {
                uint32_t b[2];
                b[0] = __float_as_uint(Vs[(ni*8 + lq)*VSTR + kb]);
                b[1] = __float_as_uint(Vs[(ni*8 + lq)*VSTR + kb + 4]);
                mma8(accO[ni], a, b);
            }
        }
    }

    // ---- finalize ----
    float inv0 = 1.f / l0, inv8 = 1.f / l8;
    __syncthreads();
    #pragma unroll
    for (int ni = 0; ni < 8; ni++) {
        int d = ni*8 + lr*2;
        Os[(n0 + lq    )*65 + d    ] = accO[ni][0]*inv0;
        Os[(n0 + lq    )*65 + d + 1] = accO[ni][1]*inv0;
        Os[(n0 + lq + 8)*65 + d    ] = accO[ni][2]*inv8;
        Os[(n0 + lq + 8)*65 + d + 1] = accO[ni][3]*inv8;
    }
    __syncthreads();
    float* op = g_ao + base;
    #pragma unroll
    for (int q = 0; q < 32; q++) {
        int i = tid + q*256;
        int d = i >> 7, n = i & 127;
        op[(size_t)d*SPATIAL + nB + n] = Os[n*65 + d];
    }
}

// ============================================================================
extern "C" void kernel_launch(void* const* d_in, const int* in_sizes, int n_in,
                              void* d_out, int out_size) {
    const float* x  = (const float*)d_in[0];
    const float* nw = (const float*)d_in[1];
    const float* nb = (const float*)d_in[2];
    const float* qw = (const float*)d_in[3];
    const float* qb = (const float*)d_in[4];
    const float* kw = (const float*)d_in[5];
    const float* kb = (const float*)d_in[6];
    const float* vw = (const float*)d_in[7];
    const float* vb = (const float*)d_in[8];
    const float* pw = (const float*)d_in[9];
    const float* pb = (const float*)d_in[10];
    float* out = (float*)d_out;
    (void)in_sizes; (void)n_in; (void)out_size;

    cudaFuncSetAttribute(flash_kernel,
                         cudaFuncAttributeMaxDynamicSharedMemorySize, (int)FL_SMEM);
    cudaFuncSetAttribute(mma_qkv,
                         cudaFuncAttributeMaxDynamicSharedMemorySize, (int)CONV_SMEM);
    cudaFuncSetAttribute(mma_proj,
                         cudaFuncAttributeMaxDynamicSharedMemorySize, (int)CONV_SMEM);

    gn_kernel<<<BATCH*8, 512>>>(x, nw, nb);

    mma_qkv<<<dim3(SPATIAL/128, 12, BATCH), 256, CONV_SMEM>>>(qw, qb, kw, kb, vw, vb);

    flash_kernel<<<dim3(SPATIAL/128, NBH), 256, FL_SMEM>>>();

    mma_proj<<<dim3(SPATIAL/128, CHANNELS/128, BATCH), 256, CONV_SMEM>>>(pw, pb, x, out);
}

// round 8
// speedup vs baseline: 9.8741x; 1.5516x over previous
#include <cuda_runtime.h>
#include <cstdint>

#define BATCH    8
#define CHANNELS 512
#define SPATIAL  1024
#define NHEADS   8
#define HDIM     64
#define GCH      64
#define NBH      (BATCH*NHEADS)
#define BC       (CHANNELS*SPATIAL)

// -------- scratch --------
__device__ float    g_xn [BATCH*BC];             // fp32 [b][c][p] (GN out)
__device__ uint16_t g_xnT[BATCH*BC];             // bf16 [b][p][c]
__device__ uint16_t g_qT [BATCH*BC];             // bf16 [b][p][c] (scale folded)
__device__ uint16_t g_kT [BATCH*BC];             // bf16 [b][p][c]
__device__ uint16_t g_v  [BATCH*BC];             // bf16 [b][c][p]
__device__ uint16_t g_aoT[BATCH*BC];             // bf16 [b][p][c]
__device__ uint16_t g_w[4][CHANNELS*CHANNELS];   // bf16 weights [o][c]
__device__ float    g_b[4][CHANNELS];

// ---------------- helpers ----------------
__device__ __forceinline__ uint32_t packbf(float lo, float hi) {
    uint32_t r;
    asm("cvt.rn.bf16x2.f32 %0, %1, %2;" : "=r"(r) : "f"(hi), "f"(lo));
    return r;
}
__device__ __forceinline__ uint16_t bf16u(float x) {
    uint16_t u;
    asm("cvt.rn.bf16.f32 %0, %1;" : "=h"(u) : "f"(x));
    return u;
}
__device__ __forceinline__ void mma16(float* c, const uint32_t* a, const uint32_t* b) {
    asm volatile("mma.sync.aligned.m16n8k16.row.col.f32.bf16.bf16.f32 "
        "{%0,%1,%2,%3}, {%4,%5,%6,%7}, {%8,%9}, {%0,%1,%2,%3};"
        : "+f"(c[0]), "+f"(c[1]), "+f"(c[2]), "+f"(c[3])
        : "r"(a[0]), "r"(a[1]), "r"(a[2]), "r"(a[3]), "r"(b[0]), "r"(b[1]));
}
__device__ __forceinline__ void cp16b(uint16_t* s, const uint16_t* g) {
    uint32_t sa = (uint32_t)__cvta_generic_to_shared(s);
    asm volatile("cp.async.cg.shared.global [%0], [%1], 16;" :: "r"(sa), "l"(g));
}
#define CP_COMMIT() asm volatile("cp.async.commit_group;" ::: "memory")
#define CP_WAIT(N)  asm volatile("cp.async.wait_group %0;" :: "n"(N) : "memory")

// ============================================================================
// GroupNorm (fp32 out)
// ============================================================================
__global__ __launch_bounds__(512) void gn_kernel(const float* __restrict__ x,
                                                 const float* __restrict__ w,
                                                 const float* __restrict__ bgn) {
    int bg = blockIdx.x;
    int b = bg >> 3, g = bg & 7;
    size_t base = (size_t)(b*CHANNELS + g*GCH) * SPATIAL;
    const float4* x4 = (const float4*)(x + base);
    float4* y4 = (float4*)(g_xn + base);
    int tid = threadIdx.x;

    float s = 0.f, ss = 0.f;
    for (int i = tid; i < GCH*SPATIAL/4; i += 512) {
        float4 v = x4[i];
        s  += v.x + v.y + v.z + v.w;
        ss += v.x*v.x + v.y*v.y + v.z*v.z + v.w*v.w;
    }
    __shared__ float rs[512], rq[512];
    rs[tid] = s; rq[tid] = ss;
    __syncthreads();
    for (int o = 256; o > 0; o >>= 1) {
        if (tid < o) { rs[tid] += rs[tid+o]; rq[tid] += rq[tid+o]; }
        __syncthreads();
    }
    float mu  = rs[0] * (1.f/65536.f);
    float var = rq[0] * (1.f/65536.f) - mu*mu;
    float rstd = rsqrtf(var + 1e-5f);

    for (int i = tid; i < GCH*SPATIAL/4; i += 512) {
        int c = g*GCH + (i >> 8);
        float wc = w[c], bc = bgn[c];
        float4 v = x4[i];
        float4 r;
        r.x = (v.x - mu) * rstd * wc + bc;
        r.y = (v.y - mu) * rstd * wc + bc;
        r.z = (v.z - mu) * rstd * wc + bc;
        r.w = (v.w - mu) * rstd * wc + bc;
        y4[i] = r;
    }
}

// ============================================================================
// Transpose+convert: g_xn fp32 [c][p] -> g_xnT bf16 [p][c]
// ============================================================================
__global__ __launch_bounds__(256) void xpose_kernel() {
    __shared__ float t[32][33];
    int b = blockIdx.z, cB = blockIdx.y*32, pB = blockIdx.x*32;
    const float* src = g_xn + (size_t)b*BC;
    int tx = threadIdx.x & 31, ty = threadIdx.x >> 5;
    #pragma unroll
    for (int j = 0; j < 4; j++)
        t[ty + j*8][tx] = src[(size_t)(cB + ty + j*8)*SPATIAL + pB + tx];
    __syncthreads();
    uint32_t* dst = (uint32_t*)(g_xnT + ((size_t)b*SPATIAL + pB)*CHANNELS + cB);
    int p = threadIdx.x >> 3, cp = (threadIdx.x & 7)*2;
    #pragma unroll
    for (int j = 0; j < 2; j++) {
        int c2 = cp + j;
        dst[(size_t)p*256 + c2] = packbf(t[c2*2][p], t[c2*2+1][p]);
    }
}

// ============================================================================
// Weight/bias prep: fp32 -> bf16, fold 0.125 into q weights+bias
// ============================================================================
__global__ __launch_bounds__(256) void wprep(const float* __restrict__ qw, const float* __restrict__ kw,
                                             const float* __restrict__ vw, const float* __restrict__ pw,
                                             const float* __restrict__ qb, const float* __restrict__ kb,
                                             const float* __restrict__ vb, const float* __restrict__ pb) {
    int g = blockIdx.x*256 + threadIdx.x;
    if (g < 4*131072) {
        int m = g >> 17, r = g & 131071;
        const float* src = m == 0 ? qw : m == 1 ? kw : m == 2 ? vw : pw;
        float sc = (m == 0) ? 0.125f : 1.f;
        float2 v = *(const float2*)&src[(size_t)r*2];
        ((uint32_t*)g_w[m])[r] = packbf(v.x*sc, v.y*sc);
    } else {
        int gb = g - 4*131072;
        if (gb < 2048) {
            int m = gb >> 9, o = gb & 511;
            const float* src = m == 0 ? qb : m == 1 ? kb : m == 2 ? vb : pb;
            g_b[m][o] = src[o] * ((m == 0) ? 0.125f : 1.f);
        }
    }
}

// ============================================================================
// Conv1x1 bf16 m16n8k16, double-buffered cp.async.
// Tile 128(o)x128(p), Kt=32. smem rows padded to 40 bf16 (20 u32).
// mode 0: bf16 transposed out [p][c]; 1: bf16 direct [o][p]; 2: fp32+bias+resid
// ============================================================================
#define CONV_SMEM (4*5120*2)   // 40960 B

__device__ __forceinline__ void conv_stage_bf(uint16_t* sA, uint16_t* sB,
                                              const uint16_t* W, const uint16_t* Xt,
                                              int k0, int tid) {
    #pragma unroll
    for (int q = 0; q < 2; q++) {
        int i = tid + q*256;
        int row = i >> 2, c = (i & 3) * 8;
        cp16b(&sA[row*40 + c], &W[(size_t)row*CHANNELS + k0 + c]);
    }
    #pragma unroll
    for (int q = 0; q < 2; q++) {
        int i = tid + q*256;
        int row = i >> 2, c = (i & 3) * 8;
        cp16b(&sB[row*40 + c], &Xt[(size_t)row*CHANNELS + k0 + c]);
    }
}

__device__ __forceinline__ void conv_core_bf(const uint16_t* __restrict__ W,
                                             const float* __restrict__ bias,
                                             const uint16_t* __restrict__ Xt,
                                             int mode,
                                             uint16_t* __restrict__ outT,
                                             uint16_t* __restrict__ outD,
                                             float* __restrict__ outF,
                                             const float* __restrict__ resid) {
    extern __shared__ __align__(16) uint16_t csm[];
    uint16_t* sA[2] = { csm, csm + 5120 };
    uint16_t* sB[2] = { csm + 10240, csm + 15360 };

    int tid = threadIdx.x, lane = tid & 31, wid = tid >> 5;
    int wy = wid & 3, wx = wid >> 2;
    int lq = lane >> 2, lr = lane & 3;

    float acc[2][8][4];
    #pragma unroll
    for (int i = 0; i < 2; i++)
        #pragma unroll
        for (int j = 0; j < 8; j++)
            #pragma unroll
            for (int t = 0; t < 4; t++) acc[i][j][t] = 0.f;

    conv_stage_bf(sA[0], sB[0], W, Xt, 0, tid);
    CP_COMMIT();

    for (int it = 0; it < 16; it++) {
        int cur = it & 1;
        if (it < 15) {
            conv_stage_bf(sA[cur^1], sB[cur^1], W, Xt, (it+1)*32, tid);
            CP_COMMIT();
            CP_WAIT(1);
        } else {
            CP_WAIT(0);
        }
        __syncthreads();

        const uint32_t* A = (const uint32_t*)sA[cur];
        const uint32_t* B = (const uint32_t*)sB[cur];
        #pragma unroll
        for (int ks = 0; ks < 2; ks++) {
            int kb = ks*8 + lr;
            uint32_t a[2][4], b[8][2];
            #pragma unroll
            for (int mi = 0; mi < 2; mi++) {
                int o = wy*32 + mi*16 + lq;
                a[mi][0] = A[o*20 + kb];
                a[mi][1] = A[(o+8)*20 + kb];
                a[mi][2] = A[o*20 + kb + 4];
                a[mi][3] = A[(o+8)*20 + kb + 4];
            }
            #pragma unroll
            for (int ni = 0; ni < 8; ni++) {
                int p = wx*64 + ni*8 + lq;
                b[ni][0] = B[p*20 + kb];
                b[ni][1] = B[p*20 + kb + 4];
            }
            #pragma unroll
            for (int mi = 0; mi < 2; mi++)
                #pragma unroll
                for (int ni = 0; ni < 8; ni++)
                    mma16(acc[mi][ni], a[mi], b[ni]);
        }
        __syncthreads();
    }

    if (mode == 2) {
        #pragma unroll
        for (int mi = 0; mi < 2; mi++) {
            int o0 = wy*32 + mi*16 + lq;
            float bi0 = bias[o0], bi8 = bias[o0+8];
            #pragma unroll
            for (int ni = 0; ni < 8; ni++) {
                int p = wx*64 + ni*8 + lr*2;
                size_t off0 = (size_t)o0*SPATIAL + p;
                size_t off8 = (size_t)(o0+8)*SPATIAL + p;
                float2 r0 = make_float2(acc[mi][ni][0] + bi0, acc[mi][ni][1] + bi0);
                float2 r8 = make_float2(acc[mi][ni][2] + bi8, acc[mi][ni][3] + bi8);
                float2 v0 = *(const float2*)&resid[off0];
                float2 v8 = *(const float2*)&resid[off8];
                r0.x += v0.x; r0.y += v0.y;
                r8.x += v8.x; r8.y += v8.y;
                *(float2*)&outF[off0] = r0;
                *(float2*)&outF[off8] = r8;
            }
        }
    } else if (mode == 1) {
        #pragma unroll
        for (int mi = 0; mi < 2; mi++) {
            int o0 = wy*32 + mi*16 + lq;
            float bi0 = bias[o0], bi8 = bias[o0+8];
            uint32_t* r0 = (uint32_t*)(outD + (size_t)o0*SPATIAL);
            uint32_t* r8 = (uint32_t*)(outD + (size_t)(o0+8)*SPATIAL);
            #pragma unroll
            for (int ni = 0; ni < 8; ni++) {
                int pc = wx*32 + ni*4 + lr;
                r0[pc] = packbf(acc[mi][ni][0] + bi0, acc[mi][ni][1] + bi0);
                r8[pc] = packbf(acc[mi][ni][2] + bi8, acc[mi][ni][3] + bi8);
            }
        }
    } else {
        // transposed bf16 out via smem
        uint16_t* Ts = csm;   // [128 p][136]
        #pragma unroll
        for (int mi = 0; mi < 2; mi++) {
            int o0 = wy*32 + mi*16 + lq;
            float bi0 = bias[o0], bi8 = bias[o0+8];
            #pragma unroll
            for (int ni = 0; ni < 8; ni++) {
                int p = wx*64 + ni*8 + lr*2;
                Ts[(p  )*136 + o0    ] = bf16u(acc[mi][ni][0] + bi0);
                Ts[(p+1)*136 + o0    ] = bf16u(acc[mi][ni][1] + bi0);
                Ts[(p  )*136 + o0 + 8] = bf16u(acc[mi][ni][2] + bi8);
                Ts[(p+1)*136 + o0 + 8] = bf16u(acc[mi][ni][3] + bi8);
            }
        }
        __syncthreads();
        #pragma unroll
        for (int q = 0; q < 8; q++) {
            int i = tid + q*256;
            int p = i >> 4, c = (i & 15) * 8;
            *(uint4*)&outT[(size_t)p*CHANNELS + c] = *(uint4*)&Ts[p*136 + c];
        }
    }
}

__global__ __launch_bounds__(256, 2) void conv_qkv_bf() {
    int b = blockIdx.z;
    int sel = blockIdx.y >> 2;
    int oB = (blockIdx.y & 3) * 128;
    int pB = blockIdx.x * 128;
    const uint16_t* W = g_w[sel] + (size_t)oB*CHANNELS;
    const float* bias = g_b[sel] + oB;
    const uint16_t* Xt = g_xnT + ((size_t)b*SPATIAL + pB)*CHANNELS;
    if (sel == 2) {
        conv_core_bf(W, bias, Xt, 1, nullptr,
                     g_v + (size_t)b*BC + (size_t)oB*SPATIAL + pB, nullptr, nullptr);
    } else {
        uint16_t* gT = (sel == 0) ? g_qT : g_kT;
        conv_core_bf(W, bias, Xt, 0,
                     gT + (size_t)b*BC + (size_t)pB*CHANNELS + oB,
                     nullptr, nullptr, nullptr);
    }
}

__global__ __launch_bounds__(256, 2) void conv_proj_bf(const float* __restrict__ x,
                                                       float* __restrict__ out) {
    int b = blockIdx.z, oB = blockIdx.y*128, pB = blockIdx.x*128;
    conv_core_bf(g_w[3] + (size_t)oB*CHANNELS, g_b[3] + oB,
                 g_aoT + ((size_t)b*SPATIAL + pB)*CHANNELS, 2,
                 nullptr, nullptr,
                 out + (size_t)b*BC + (size_t)oB*SPATIAL + pB,
                 x + (size_t)b*BC + (size_t)oB*SPATIAL + pB);
}

// ============================================================================
// Flash attention bf16: CTA per (bh, 128-q tile), m-tile 64, double-buffered K/V.
// Q/K from [p][d] bf16, V from [d][p] bf16, out -> aoT [p][c] bf16.
// ============================================================================
#define FQ  0
#define FK0 9216
#define FK1 13824
#define FV0 18432
#define FV1 23040
#define FP  27648
#define FL_SMEM ((27648 + 9216) * 2)   // 73728 B

__global__ __launch_bounds__(256, 2) void flash_bf() {
    extern __shared__ __align__(16) uint16_t fsm[];
    int nB = blockIdx.x * 128;
    int bh = blockIdx.y;
    int b = bh >> 3, h = bh & 7;
    const uint16_t* qT = g_qT + (size_t)b*BC + h*HDIM;
    const uint16_t* kT = g_kT + (size_t)b*BC + h*HDIM;
    const uint16_t* vB = g_v  + (size_t)b*BC + (size_t)h*HDIM*SPATIAL;
    uint16_t* aoT      = g_aoT + (size_t)b*BC + h*HDIM;

    int tid = threadIdx.x, lane = tid & 31, wid = tid >> 5;
    int lq = lane >> 2, lr = lane & 3;
    int n0 = wid * 16;

    // stage Q [n][d]
    #pragma unroll
    for (int q = 0; q < 4; q++) {
        int i = tid + q*256;
        int row = i >> 3, c = (i & 7) * 8;
        cp16b(&fsm[FQ + row*72 + c], &qT[(size_t)(nB + row)*CHANNELS + c]);
    }
    // stage K/V tile 0
    #pragma unroll
    for (int q = 0; q < 2; q++) {
        int i = tid + q*256;
        int row = i >> 3, c = (i & 7) * 8;
        cp16b(&fsm[FK0 + row*72 + c], &kT[(size_t)row*CHANNELS + c]);
        cp16b(&fsm[FV0 + row*72 + c], &vB[(size_t)row*SPATIAL + c]);
    }
    CP_COMMIT();

    float accO[8][4];
    #pragma unroll
    for (int i = 0; i < 8; i++)
        #pragma unroll
        for (int t = 0; t < 4; t++) accO[i][t] = 0.f;
    float mPrev0 = -1e30f, mPrev8 = -1e30f;
    float l0 = 0.f, l8 = 0.f;

    for (int it = 0; it < 16; it++) {
        int cur = it & 1;
        if (it < 15) {
            int m1 = (it+1)*64;
            uint16_t* Kn = fsm + (cur ? FK0 : FK1);
            uint16_t* Vn = fsm + (cur ? FV0 : FV1);
            #pragma unroll
            for (int q = 0; q < 2; q++) {
                int i = tid + q*256;
                int row = i >> 3, c = (i & 7) * 8;
                cp16b(&Kn[row*72 + c], &kT[(size_t)(m1 + row)*CHANNELS + c]);
                cp16b(&Vn[row*72 + c], &vB[(size_t)row*SPATIAL + m1 + c]);
            }
            CP_COMMIT();
            CP_WAIT(1);
        } else {
            CP_WAIT(0);
        }
        __syncthreads();

        const uint32_t* Q32 = (const uint32_t*)(fsm + FQ);
        const uint32_t* K32 = (const uint32_t*)(fsm + (cur ? FK1 : FK0));
        const uint32_t* V32 = (const uint32_t*)(fsm + (cur ? FV1 : FV0));
        uint32_t* P32 = (uint32_t*)(fsm + FP);

        // ---- S = Q K^T ----
        float accS[8][4];
        #pragma unroll
        for (int i = 0; i < 8; i++)
            #pragma unroll
            for (int t = 0; t < 4; t++) accS[i][t] = 0.f;
        #pragma unroll
        for (int ks = 0; ks < 4; ks++) {
            int kb = ks*8 + lr;
            uint32_t a[4];
            a[0] = Q32[(n0 + lq)*36 + kb];
            a[1] = Q32[(n0 + lq + 8)*36 + kb];
            a[2] = Q32[(n0 + lq)*36 + kb + 4];
            a[3] = Q32[(n0 + lq + 8)*36 + kb + 4];
            #pragma unroll
            for (int ni = 0; ni < 8; ni++) {
                uint32_t bb[2];
                bb[0] = K32[(ni*8 + lq)*36 + kb];
                bb[1] = K32[(ni*8 + lq)*36 + kb + 4];
                mma16(accS[ni], a, bb);
            }
        }

        // ---- online softmax ----
        float tm0 = -1e30f, tm8 = -1e30f;
        #pragma unroll
        for (int ni = 0; ni < 8; ni++) {
            tm0 = fmaxf(tm0, fmaxf(accS[ni][0], accS[ni][1]));
            tm8 = fmaxf(tm8, fmaxf(accS[ni][2], accS[ni][3]));
        }
        tm0 = fmaxf(tm0, __shfl_xor_sync(0xffffffffu, tm0, 1));
        tm0 = fmaxf(tm0, __shfl_xor_sync(0xffffffffu, tm0, 2));
        tm8 = fmaxf(tm8, __shfl_xor_sync(0xffffffffu, tm8, 1));
        tm8 = fmaxf(tm8, __shfl_xor_sync(0xffffffffu, tm8, 2));

        float mNew0 = fmaxf(mPrev0, tm0);
        float mNew8 = fmaxf(mPrev8, tm8);
        float alpha0 = __expf(mPrev0 - mNew0);
        float alpha8 = __expf(mPrev8 - mNew8);
        mPrev0 = mNew0; mPrev8 = mNew8;

        float sum0 = 0.f, sum8 = 0.f;
        #pragma unroll
        for (int ni = 0; ni < 8; ni++) {
            float p0 = __expf(accS[ni][0] - mNew0);
            float p1 = __expf(accS[ni][1] - mNew0);
            float p2 = __expf(accS[ni][2] - mNew8);
            float p3 = __expf(accS[ni][3] - mNew8);
            sum0 += p0 + p1; sum8 += p2 + p3;
            P32[(n0 + lq)*36 + ni*4 + lr]     = packbf(p0, p1);
            P32[(n0 + lq + 8)*36 + ni*4 + lr] = packbf(p2, p3);
        }
        __syncwarp();
        sum0 += __shfl_xor_sync(0xffffffffu, sum0, 1);
        sum0 += __shfl_xor_sync(0xffffffffu, sum0, 2);
        sum8 += __shfl_xor_sync(0xffffffffu, sum8, 1);
        sum8 += __shfl_xor_sync(0xffffffffu, sum8, 2);
        l0 = l0*alpha0 + sum0;
        l8 = l8*alpha8 + sum8;

        #pragma unroll
        for (int ni = 0; ni < 8; ni++) {
            accO[ni][0] *= alpha0; accO[ni][1] *= alpha0;
            accO[ni][2] *= alpha8; accO[ni][3] *= alpha8;
        }

        // ---- O += P V^T ----
        #pragma unroll
        for (int ks = 0; ks < 4; ks++) {
            int kb = ks*8 + lr;
            uint32_t a[4];
            a[0] = P32[(n0 + lq)*36 + kb];
            a[1] = P32[(n0 + lq + 8)*36 + kb];
            a[2] = P32[(n0 + lq)*36 + kb + 4];
            a[3] = P32[(n0 + lq + 8)*36 + kb + 4];
            #pragma unroll
            for (int ni = 0; ni < 8; ni++) {
                uint32_t bb[2];
                bb[0] = V32[(ni*8 + lq)*36 + kb];
                bb[1] = V32[(ni*8 + lq)*36 + kb + 4];
                mma16(accO[ni], a, bb);
            }
        }
        __syncthreads();
    }

    // ---- finalize: direct bf16 store to aoT [p][c] ----
    float inv0 = 1.f / l0, inv8 = 1.f / l8;
    uint32_t* r0 = (uint32_t*)(aoT + (size_t)(nB + n0 + lq)*CHANNELS);
    uint32_t* r8 = (uint32_t*)(aoT + (size_t)(nB + n0 + lq + 8)*CHANNELS);
    #pragma unroll
    for (int ni = 0; ni < 8; ni++) {
        r0[ni*4 + lr] = packbf(accO[ni][0]*inv0, accO[ni][1]*inv0);
        r8[ni*4 + lr] = packbf(accO[ni][2]*inv8, accO[ni][3]*inv8);
    }
}

// ============================================================================
extern "C" void kernel_launch(void* const* d_in, const int* in_sizes, int n_in,
                              void* d_out, int out_size) {
    const float* x  = (const float*)d_in[0];
    const float* nw = (const float*)d_in[1];
    const float* nb = (const float*)d_in[2];
    const float* qw = (const float*)d_in[3];
    const float* qb = (const float*)d_in[4];
    const float* kw = (const float*)d_in[5];
    const float* kb = (const float*)d_in[6];
    const float* vw = (const float*)d_in[7];
    const float* vb = (const float*)d_in[8];
    const float* pw = (const float*)d_in[9];
    const float* pb = (const float*)d_in[10];
    float* out = (float*)d_out;
    (void)in_sizes; (void)n_in; (void)out_size;

    cudaFuncSetAttribute(flash_bf,
                         cudaFuncAttributeMaxDynamicSharedMemorySize, (int)FL_SMEM);

    wprep<<<2056, 256>>>(qw, kw, vw, pw, qb, kb, vb, pb);
    gn_kernel<<<BATCH*8, 512>>>(x, nw, nb);
    xpose_kernel<<<dim3(SPATIAL/32, CHANNELS/32, BATCH), 256>>>();

    conv_qkv_bf<<<dim3(SPATIAL/128, 12, BATCH), 256, CONV_SMEM>>>();

    flash_bf<<<dim3(SPATIAL/128, NBH), 256, FL_SMEM>>>();

    conv_proj_bf<<<dim3(SPATIAL/128, CHANNELS/128, BATCH), 256, CONV_SMEM>>>(x, out);
}

// round 9
// speedup vs baseline: 11.3591x; 1.1504x over previous
#include <cuda_runtime.h>
#include <cstdint>

#define BATCH    8
#define CHANNELS 512
#define SPATIAL  1024
#define NHEADS   8
#define HDIM     64
#define GCH      64
#define NBH      (BATCH*NHEADS)
#define BC       (CHANNELS*SPATIAL)

// -------- scratch --------
__device__ float    g_xn [BATCH*BC];             // fp32 [b][c][p]
__device__ uint16_t g_xnT[BATCH*BC];             // bf16 [b][p][c]
__device__ uint16_t g_qT [BATCH*BC];             // bf16 [b][p][c] (scale folded)
__device__ uint16_t g_kT [BATCH*BC];             // bf16 [b][p][c]
__device__ uint16_t g_v  [BATCH*BC];             // bf16 [b][c][p]
__device__ uint16_t g_aoT[BATCH*BC];             // bf16 [b][p][c]
__device__ uint16_t g_w[4][CHANNELS*CHANNELS];   // bf16 [o][c]
__device__ float    g_b[4][CHANNELS];

// ---------------- helpers ----------------
__device__ __forceinline__ uint32_t packbf(float lo, float hi) {
    uint32_t r;
    asm("cvt.rn.bf16x2.f32 %0, %1, %2;" : "=r"(r) : "f"(hi), "f"(lo));
    return r;
}
__device__ __forceinline__ uint16_t bf16u(float x) {
    uint16_t u;
    asm("cvt.rn.bf16.f32 %0, %1;" : "=h"(u) : "f"(x));
    return u;
}
__device__ __forceinline__ void mma16(float* c, const uint32_t* a, const uint32_t* b) {
    asm volatile("mma.sync.aligned.m16n8k16.row.col.f32.bf16.bf16.f32 "
        "{%0,%1,%2,%3}, {%4,%5,%6,%7}, {%8,%9}, {%0,%1,%2,%3};"
        : "+f"(c[0]), "+f"(c[1]), "+f"(c[2]), "+f"(c[3])
        : "r"(a[0]), "r"(a[1]), "r"(a[2]), "r"(a[3]), "r"(b[0]), "r"(b[1]));
}
__device__ __forceinline__ void ldm4(uint32_t* r, uint32_t saddr) {
    asm volatile("ldmatrix.sync.aligned.m8n8.x4.shared.b16 {%0,%1,%2,%3}, [%4];"
        : "=r"(r[0]), "=r"(r[1]), "=r"(r[2]), "=r"(r[3]) : "r"(saddr));
}
__device__ __forceinline__ void cp16b(uint16_t* s, const uint16_t* g) {
    uint32_t sa = (uint32_t)__cvta_generic_to_shared(s);
    asm volatile("cp.async.cg.shared.global [%0], [%1], 16;" :: "r"(sa), "l"(g));
}
#define CP_COMMIT() asm volatile("cp.async.commit_group;" ::: "memory")
#define CP_WAIT(N)  asm volatile("cp.async.wait_group %0;" :: "n"(N) : "memory")

// ============================================================================
// GroupNorm (fp32 out)
// ============================================================================
__global__ __launch_bounds__(512) void gn_kernel(const float* __restrict__ x,
                                                 const float* __restrict__ w,
                                                 const float* __restrict__ bgn) {
    int bg = blockIdx.x;
    int b = bg >> 3, g = bg & 7;
    size_t base = (size_t)(b*CHANNELS + g*GCH) * SPATIAL;
    const float4* x4 = (const float4*)(x + base);
    float4* y4 = (float4*)(g_xn + base);
    int tid = threadIdx.x;

    float s = 0.f, ss = 0.f;
    for (int i = tid; i < GCH*SPATIAL/4; i += 512) {
        float4 v = x4[i];
        s  += v.x + v.y + v.z + v.w;
        ss += v.x*v.x + v.y*v.y + v.z*v.z + v.w*v.w;
    }
    __shared__ float rs[512], rq[512];
    rs[tid] = s; rq[tid] = ss;
    __syncthreads();
    for (int o = 256; o > 0; o >>= 1) {
        if (tid < o) { rs[tid] += rs[tid+o]; rq[tid] += rq[tid+o]; }
        __syncthreads();
    }
    float mu  = rs[0] * (1.f/65536.f);
    float var = rq[0] * (1.f/65536.f) - mu*mu;
    float rstd = rsqrtf(var + 1e-5f);

    for (int i = tid; i < GCH*SPATIAL/4; i += 512) {
        int c = g*GCH + (i >> 8);
        float wc = w[c], bc = bgn[c];
        float4 v = x4[i];
        float4 r;
        r.x = (v.x - mu) * rstd * wc + bc;
        r.y = (v.y - mu) * rstd * wc + bc;
        r.z = (v.z - mu) * rstd * wc + bc;
        r.w = (v.w - mu) * rstd * wc + bc;
        y4[i] = r;
    }
}

// ============================================================================
// Transpose+convert: g_xn fp32 [c][p] -> g_xnT bf16 [p][c]
// ============================================================================
__global__ __launch_bounds__(256) void xpose_kernel() {
    __shared__ float t[32][33];
    int b = blockIdx.z, cB = blockIdx.y*32, pB = blockIdx.x*32;
    const float* src = g_xn + (size_t)b*BC;
    int tx = threadIdx.x & 31, ty = threadIdx.x >> 5;
    #pragma unroll
    for (int j = 0; j < 4; j++)
        t[ty + j*8][tx] = src[(size_t)(cB + ty + j*8)*SPATIAL + pB + tx];
    __syncthreads();
    uint32_t* dst = (uint32_t*)(g_xnT + ((size_t)b*SPATIAL + pB)*CHANNELS + cB);
    int p = threadIdx.x >> 3, cp = (threadIdx.x & 7)*2;
    #pragma unroll
    for (int j = 0; j < 2; j++) {
        int c2 = cp + j;
        dst[(size_t)p*256 + c2] = packbf(t[c2*2][p], t[c2*2+1][p]);
    }
}

// ============================================================================
// Weight/bias prep
// ============================================================================
__global__ __launch_bounds__(256) void wprep(const float* __restrict__ qw, const float* __restrict__ kw,
                                             const float* __restrict__ vw, const float* __restrict__ pw,
                                             const float* __restrict__ qb, const float* __restrict__ kb,
                                             const float* __restrict__ vb, const float* __restrict__ pb) {
    int g = blockIdx.x*256 + threadIdx.x;
    if (g < 4*131072) {
        int m = g >> 17, r = g & 131071;
        const float* src = m == 0 ? qw : m == 1 ? kw : m == 2 ? vw : pw;
        float sc = (m == 0) ? 0.125f : 1.f;
        float2 v = *(const float2*)&src[(size_t)r*2];
        ((uint32_t*)g_w[m])[r] = packbf(v.x*sc, v.y*sc);
    } else {
        int gb = g - 4*131072;
        if (gb < 2048) {
            int m = gb >> 9, o = gb & 511;
            const float* src = m == 0 ? qb : m == 1 ? kb : m == 2 ? vb : pb;
            g_b[m][o] = src[o] * ((m == 0) ? 0.125f : 1.f);
        }
    }
}

// ============================================================================
// Conv1x1 bf16 m16n8k16 + ldmatrix, double-buffered cp.async.
// Tile 128(o)x128(p), Kt=32. smem rows 40 halves (80 B).
// ============================================================================
#define CONV_SMEM (4*5120*2)   // 40960 B

__device__ __forceinline__ void conv_stage_bf(uint16_t* sA, uint16_t* sB,
                                              const uint16_t* W, const uint16_t* Xt,
                                              int k0, int tid) {
    #pragma unroll
    for (int q = 0; q < 2; q++) {
        int i = tid + q*256;
        int row = i >> 2, c = (i & 3) * 8;
        cp16b(&sA[row*40 + c], &W[(size_t)row*CHANNELS + k0 + c]);
    }
    #pragma unroll
    for (int q = 0; q < 2; q++) {
        int i = tid + q*256;
        int row = i >> 2, c = (i & 3) * 8;
        cp16b(&sB[row*40 + c], &Xt[(size_t)row*CHANNELS + k0 + c]);
    }
}

__device__ __forceinline__ void conv_core_bf(const uint16_t* __restrict__ W,
                                             const float* __restrict__ bias,
                                             const uint16_t* __restrict__ Xt,
                                             int mode,
                                             uint16_t* __restrict__ outT,
                                             uint16_t* __restrict__ outD,
                                             float* __restrict__ outF,
                                             const float* __restrict__ resid) {
    extern __shared__ __align__(16) uint16_t csm[];
    uint16_t* sA[2] = { csm, csm + 5120 };
    uint16_t* sB[2] = { csm + 10240, csm + 15360 };

    int tid = threadIdx.x, lane = tid & 31, wid = tid >> 5;
    int wy = wid & 3, wx = wid >> 2;
    int lq = lane >> 2, lr = lane & 3;

    // ldmatrix per-lane byte offsets (80 B rows)
    uint32_t aoff = (lane & 15)*80 + (lane >> 4)*16;
    uint32_t boff = (lane & 7)*80 + ((lane >> 3) & 1)*16 + (lane >> 4)*640;

    float acc[2][8][4];
    #pragma unroll
    for (int i = 0; i < 2; i++)
        #pragma unroll
        for (int j = 0; j < 8; j++)
            #pragma unroll
            for (int t = 0; t < 4; t++) acc[i][j][t] = 0.f;

    conv_stage_bf(sA[0], sB[0], W, Xt, 0, tid);
    CP_COMMIT();

    for (int it = 0; it < 16; it++) {
        int cur = it & 1;
        if (it < 15) {
            conv_stage_bf(sA[cur^1], sB[cur^1], W, Xt, (it+1)*32, tid);
            CP_COMMIT();
            CP_WAIT(1);
        } else {
            CP_WAIT(0);
        }
        __syncthreads();

        uint32_t sAa = (uint32_t)__cvta_generic_to_shared(sA[cur]);
        uint32_t sBa = (uint32_t)__cvta_generic_to_shared(sB[cur]);
        #pragma unroll
        for (int ks = 0; ks < 2; ks++) {
            uint32_t a[2][4], b[4][4];
            #pragma unroll
            for (int mi = 0; mi < 2; mi++)
                ldm4(a[mi], sAa + (wy*32 + mi*16)*80 + ks*32 + aoff);
            #pragma unroll
            for (int pp = 0; pp < 4; pp++)
                ldm4(b[pp], sBa + (wx*64 + pp*16)*80 + ks*32 + boff);
            #pragma unroll
            for (int mi = 0; mi < 2; mi++)
                #pragma unroll
                for (int pp = 0; pp < 4; pp++) {
                    mma16(acc[mi][2*pp],   a[mi], &b[pp][0]);
                    mma16(acc[mi][2*pp+1], a[mi], &b[pp][2]);
                }
        }
        __syncthreads();
    }

    if (mode == 2) {
        #pragma unroll
        for (int mi = 0; mi < 2; mi++) {
            int o0 = wy*32 + mi*16 + lq;
            float bi0 = bias[o0], bi8 = bias[o0+8];
            #pragma unroll
            for (int ni = 0; ni < 8; ni++) {
                int p = wx*64 + ni*8 + lr*2;
                size_t off0 = (size_t)o0*SPATIAL + p;
                size_t off8 = (size_t)(o0+8)*SPATIAL + p;
                float2 r0 = make_float2(acc[mi][ni][0] + bi0, acc[mi][ni][1] + bi0);
                float2 r8 = make_float2(acc[mi][ni][2] + bi8, acc[mi][ni][3] + bi8);
                float2 v0 = *(const float2*)&resid[off0];
                float2 v8 = *(const float2*)&resid[off8];
                r0.x += v0.x; r0.y += v0.y;
                r8.x += v8.x; r8.y += v8.y;
                *(float2*)&outF[off0] = r0;
                *(float2*)&outF[off8] = r8;
            }
        }
    } else if (mode == 1) {
        #pragma unroll
        for (int mi = 0; mi < 2; mi++) {
            int o0 = wy*32 + mi*16 + lq;
            float bi0 = bias[o0], bi8 = bias[o0+8];
            uint32_t* r0 = (uint32_t*)(outD + (size_t)o0*SPATIAL);
            uint32_t* r8 = (uint32_t*)(outD + (size_t)(o0+8)*SPATIAL);
            #pragma unroll
            for (int ni = 0; ni < 8; ni++) {
                int pc = wx*32 + ni*4 + lr;
                r0[pc] = packbf(acc[mi][ni][0] + bi0, acc[mi][ni][1] + bi0);
                r8[pc] = packbf(acc[mi][ni][2] + bi8, acc[mi][ni][3] + bi8);
            }
        }
    } else {
        uint16_t* Ts = csm;   // [128 p][136]
        #pragma unroll
        for (int mi = 0; mi < 2; mi++) {
            int o0 = wy*32 + mi*16 + lq;
            float bi0 = bias[o0], bi8 = bias[o0+8];
            #pragma unroll
            for (int ni = 0; ni < 8; ni++) {
                int p = wx*64 + ni*8 + lr*2;
                Ts[(p  )*136 + o0    ] = bf16u(acc[mi][ni][0] + bi0);
                Ts[(p+1)*136 + o0    ] = bf16u(acc[mi][ni][1] + bi0);
                Ts[(p  )*136 + o0 + 8] = bf16u(acc[mi][ni][2] + bi8);
                Ts[(p+1)*136 + o0 + 8] = bf16u(acc[mi][ni][3] + bi8);
            }
        }
        __syncthreads();
        #pragma unroll
        for (int q = 0; q < 8; q++) {
            int i = tid + q*256;
            int p = i >> 4, c = (i & 15) * 8;
            *(uint4*)&outT[(size_t)p*CHANNELS + c] = *(uint4*)&Ts[p*136 + c];
        }
    }
}

__global__ __launch_bounds__(256, 2) void conv_qkv_bf() {
    int b = blockIdx.z;
    int sel = blockIdx.y >> 2;
    int oB = (blockIdx.y & 3) * 128;
    int pB = blockIdx.x * 128;
    const uint16_t* W = g_w[sel] + (size_t)oB*CHANNELS;
    const float* bias = g_b[sel] + oB;
    const uint16_t* Xt = g_xnT + ((size_t)b*SPATIAL + pB)*CHANNELS;
    if (sel == 2) {
        conv_core_bf(W, bias, Xt, 1, nullptr,
                     g_v + (size_t)b*BC + (size_t)oB*SPATIAL + pB, nullptr, nullptr);
    } else {
        uint16_t* gT = (sel == 0) ? g_qT : g_kT;
        conv_core_bf(W, bias, Xt, 0,
                     gT + (size_t)b*BC + (size_t)pB*CHANNELS + oB,
                     nullptr, nullptr, nullptr);
    }
}

__global__ __launch_bounds__(256, 2) void conv_proj_bf(const float* __restrict__ x,
                                                       float* __restrict__ out) {
    int b = blockIdx.z, oB = blockIdx.y*128, pB = blockIdx.x*128;
    conv_core_bf(g_w[3] + (size_t)oB*CHANNELS, g_b[3] + oB,
                 g_aoT + ((size_t)b*SPATIAL + pB)*CHANNELS, 2,
                 nullptr, nullptr,
                 out + (size_t)b*BC + (size_t)oB*SPATIAL + pB,
                 x + (size_t)b*BC + (size_t)oB*SPATIAL + pB);
}

// ============================================================================
// Flash attention bf16 + ldmatrix + register-resident P.
// CTA per (bh, 128-q tile), m-tile 64, double-buffered K/V.
// smem halves: Q[128][72] | K0[64][72] | K1 | V0[64][72] | V1  = 27648 halves
// ============================================================================
#define FQ  0
#define FK0 9216
#define FK1 13824
#define FV0 18432
#define FV1 23040
#define FL_SMEM (27648 * 2)   // 55296 B

__global__ __launch_bounds__(256, 2) void flash_bf() {
    extern __shared__ __align__(16) uint16_t fsm[];
    int nB = blockIdx.x * 128;
    int bh = blockIdx.y;
    int b = bh >> 3, h = bh & 7;
    const uint16_t* qT = g_qT + (size_t)b*BC + h*HDIM;
    const uint16_t* kT = g_kT + (size_t)b*BC + h*HDIM;
    const uint16_t* vB = g_v  + (size_t)b*BC + (size_t)h*HDIM*SPATIAL;
    uint16_t* aoT      = g_aoT + (size_t)b*BC + h*HDIM;

    int tid = threadIdx.x, lane = tid & 31, wid = tid >> 5;
    int lq = lane >> 2, lr = lane & 3;
    int n0 = wid * 16;

    // ldmatrix per-lane byte offsets (144 B rows)
    uint32_t aoff = (lane & 15)*144 + (lane >> 4)*16;
    uint32_t boff = (lane & 7)*144 + ((lane >> 3) & 1)*16 + (lane >> 4)*1152;

    // stage Q [n][d]
    #pragma unroll
    for (int q = 0; q < 4; q++) {
        int i = tid + q*256;
        int row = i >> 3, c = (i & 7) * 8;
        cp16b(&fsm[FQ + row*72 + c], &qT[(size_t)(nB + row)*CHANNELS + c]);
    }
    #pragma unroll
    for (int q = 0; q < 2; q++) {
        int i = tid + q*256;
        int row = i >> 3, c = (i & 7) * 8;
        cp16b(&fsm[FK0 + row*72 + c], &kT[(size_t)row*CHANNELS + c]);
        cp16b(&fsm[FV0 + row*72 + c], &vB[(size_t)row*SPATIAL + c]);
    }
    CP_COMMIT();

    float accO[8][4];
    #pragma unroll
    for (int i = 0; i < 8; i++)
        #pragma unroll
        for (int t = 0; t < 4; t++) accO[i][t] = 0.f;
    float mPrev0 = -1e30f, mPrev8 = -1e30f;
    float l0 = 0.f, l8 = 0.f;

    uint32_t Qa = (uint32_t)__cvta_generic_to_shared(fsm + FQ) + n0*144 + aoff;

    for (int it = 0; it < 16; it++) {
        int cur = it & 1;
        if (it < 15) {
            int m1 = (it+1)*64;
            uint16_t* Kn = fsm + (cur ? FK0 : FK1);
            uint16_t* Vn = fsm + (cur ? FV0 : FV1);
            #pragma unroll
            for (int q = 0; q < 2; q++) {
                int i = tid + q*256;
                int row = i >> 3, c = (i & 7) * 8;
                cp16b(&Kn[row*72 + c], &kT[(size_t)(m1 + row)*CHANNELS + c]);
                cp16b(&Vn[row*72 + c], &vB[(size_t)row*SPATIAL + m1 + c]);
            }
            CP_COMMIT();
            CP_WAIT(1);
        } else {
            CP_WAIT(0);
        }
        __syncthreads();

        uint32_t Ka = (uint32_t)__cvta_generic_to_shared(fsm + (cur ? FK1 : FK0)) + boff;
        uint32_t Va = (uint32_t)__cvta_generic_to_shared(fsm + (cur ? FV1 : FV0)) + boff;

        // ---- S = Q K^T ----
        float accS[8][4];
        #pragma unroll
        for (int i = 0; i < 8; i++)
            #pragma unroll
            for (int t = 0; t < 4; t++) accS[i][t] = 0.f;
        #pragma unroll
        for (int ks = 0; ks < 4; ks++) {
            uint32_t a[4];
            ldm4(a, Qa + ks*32);
            #pragma unroll
            for (int pp = 0; pp < 4; pp++) {
                uint32_t bb[4];
                ldm4(bb, Ka + pp*2304 + ks*32);
                mma16(accS[2*pp],   a, &bb[0]);
                mma16(accS[2*pp+1], a, &bb[2]);
            }
        }

        // ---- online softmax ----
        float tm0 = -1e30f, tm8 = -1e30f;
        #pragma unroll
        for (int ni = 0; ni < 8; ni++) {
            tm0 = fmaxf(tm0, fmaxf(accS[ni][0], accS[ni][1]));
            tm8 = fmaxf(tm8, fmaxf(accS[ni][2], accS[ni][3]));
        }
        tm0 = fmaxf(tm0, __shfl_xor_sync(0xffffffffu, tm0, 1));
        tm0 = fmaxf(tm0, __shfl_xor_sync(0xffffffffu, tm0, 2));
        tm8 = fmaxf(tm8, __shfl_xor_sync(0xffffffffu, tm8, 1));
        tm8 = fmaxf(tm8, __shfl_xor_sync(0xffffffffu, tm8, 2));

        float mNew0 = fmaxf(mPrev0, tm0);
        float mNew8 = fmaxf(mPrev8, tm8);
        float alpha0 = __expf(mPrev0 - mNew0);
        float alpha8 = __expf(mPrev8 - mNew8);
        mPrev0 = mNew0; mPrev8 = mNew8;

        uint32_t pk0[8], pk8[8];
        float sum0 = 0.f, sum8 = 0.f;
        #pragma unroll
        for (int ni = 0; ni < 8; ni++) {
            float p0 = __expf(accS[ni][0] - mNew0);
            float p1 = __expf(accS[ni][1] - mNew0);
            float p2 = __expf(accS[ni][2] - mNew8);
            float p3 = __expf(accS[ni][3] - mNew8);
            sum0 += p0 + p1; sum8 += p2 + p3;
            pk0[ni] = packbf(p0, p1);
            pk8[ni] = packbf(p2, p3);
        }
        sum0 += __shfl_xor_sync(0xffffffffu, sum0, 1);
        sum0 += __shfl_xor_sync(0xffffffffu, sum0, 2);
        sum8 += __shfl_xor_sync(0xffffffffu, sum8, 1);
        sum8 += __shfl_xor_sync(0xffffffffu, sum8, 2);
        l0 = l0*alpha0 + sum0;
        l8 = l8*alpha8 + sum8;

        #pragma unroll
        for (int ni = 0; ni < 8; ni++) {
            accO[ni][0] *= alpha0; accO[ni][1] *= alpha0;
            accO[ni][2] *= alpha8; accO[ni][3] *= alpha8;
        }

        // ---- O += P V^T (A fragment direct from registers) ----
        #pragma unroll
        for (int ks = 0; ks < 4; ks++) {
            uint32_t a[4] = { pk0[2*ks], pk8[2*ks], pk0[2*ks+1], pk8[2*ks+1] };
            #pragma unroll
            for (int pp = 0; pp < 4; pp++) {
                uint32_t bb[4];
                ldm4(bb, Va + pp*2304 + ks*32);
                mma16(accO[2*pp],   a, &bb[0]);
                mma16(accO[2*pp+1], a, &bb[2]);
            }
        }
        __syncthreads();
    }

    // ---- finalize: direct bf16 store to aoT [p][c] ----
    float inv0 = 1.f / l0, inv8 = 1.f / l8;
    uint32_t* r0 = (uint32_t*)(aoT + (size_t)(nB + n0 + lq)*CHANNELS);
    uint32_t* r8 = (uint32_t*)(aoT + (size_t)(nB + n0 + lq + 8)*CHANNELS);
    #pragma unroll
    for (int ni = 0; ni < 8; ni++) {
        r0[ni*4 + lr] = packbf(accO[ni][0]*inv0, accO[ni][1]*inv0);
        r8[ni*4 + lr] = packbf(accO[ni][2]*inv8, accO[ni][3]*inv8);
    }
}

// ============================================================================
extern "C" void kernel_launch(void* const* d_in, const int* in_sizes, int n_in,
                              void* d_out, int out_size) {
    const float* x  = (const float*)d_in[0];
    const float* nw = (const float*)d_in[1];
    const float* nb = (const float*)d_in[2];
    const float* qw = (const float*)d_in[3];
    const float* qb = (const float*)d_in[4];
    const float* kw = (const float*)d_in[5];
    const float* kb = (const float*)d_in[6];
    const float* vw = (const float*)d_in[7];
    const float* vb = (const float*)d_in[8];
    const float* pw = (const float*)d_in[9];
    const float* pb = (const float*)d_in[10];
    float* out = (float*)d_out;
    (void)in_sizes; (void)n_in; (void)out_size;

    cudaFuncSetAttribute(flash_bf,
                         cudaFuncAttributeMaxDynamicSharedMemorySize, (int)FL_SMEM);

    wprep<<<2056, 256>>>(qw, kw, vw, pw, qb, kb, vb, pb);
    gn_kernel<<<BATCH*8, 512>>>(x, nw, nb);
    xpose_kernel<<<dim3(SPATIAL/32, CHANNELS/32, BATCH), 256>>>();

    conv_qkv_bf<<<dim3(SPATIAL/128, 12, BATCH), 256, CONV_SMEM>>>();

    flash_bf<<<dim3(SPATIAL/128, NBH), 256, FL_SMEM>>>();

    conv_proj_bf<<<dim3(SPATIAL/128, CHANNELS/128, BATCH), 256, CONV_SMEM>>>(x, out);
}

// round 10
// speedup vs baseline: 13.2630x; 1.1676x over previous
#include <cuda_runtime.h>
#include <cstdint>

#define BATCH    8
#define CHANNELS 512
#define SPATIAL  1024
#define NHEADS   8
#define HDIM     64
#define GCH      64
#define NBH      (BATCH*NHEADS)
#define BC       (CHANNELS*SPATIAL)

// -------- scratch --------
__device__ uint16_t g_xnT[BATCH*BC];             // bf16 [b][p][c]
__device__ uint16_t g_qT [BATCH*BC];             // bf16 [b][p][c] (scale folded)
__device__ uint16_t g_kT [BATCH*BC];             // bf16 [b][p][c]
__device__ uint16_t g_v  [BATCH*BC];             // bf16 [b][c][p]
__device__ uint16_t g_aoT[BATCH*BC];             // bf16 [b][p][c]
__device__ uint16_t g_w[4][CHANNELS*CHANNELS];   // bf16 [o][c]
__device__ float    g_b[4][CHANNELS];

// ---------------- helpers ----------------
__device__ __forceinline__ uint32_t packbf(float lo, float hi) {
    uint32_t r;
    asm("cvt.rn.bf16x2.f32 %0, %1, %2;" : "=r"(r) : "f"(hi), "f"(lo));
    return r;
}
__device__ __forceinline__ uint16_t bf16u(float x) {
    uint16_t u;
    asm("cvt.rn.bf16.f32 %0, %1;" : "=h"(u) : "f"(x));
    return u;
}
__device__ __forceinline__ void mma16(float* c, const uint32_t* a, const uint32_t* b) {
    asm volatile("mma.sync.aligned.m16n8k16.row.col.f32.bf16.bf16.f32 "
        "{%0,%1,%2,%3}, {%4,%5,%6,%7}, {%8,%9}, {%0,%1,%2,%3};"
        : "+f"(c[0]), "+f"(c[1]), "+f"(c[2]), "+f"(c[3])
        : "r"(a[0]), "r"(a[1]), "r"(a[2]), "r"(a[3]), "r"(b[0]), "r"(b[1]));
}
__device__ __forceinline__ void ldm4(uint32_t* r, uint32_t saddr) {
    asm volatile("ldmatrix.sync.aligned.m8n8.x4.shared.b16 {%0,%1,%2,%3}, [%4];"
        : "=r"(r[0]), "=r"(r[1]), "=r"(r[2]), "=r"(r[3]) : "r"(saddr));
}
__device__ __forceinline__ void cp16b(uint16_t* s, const uint16_t* g) {
    uint32_t sa = (uint32_t)__cvta_generic_to_shared(s);
    asm volatile("cp.async.cg.shared.global [%0], [%1], 16;" :: "r"(sa), "l"(g));
}
#define CP_COMMIT() asm volatile("cp.async.commit_group;" ::: "memory")
#define CP_WAIT(N)  asm volatile("cp.async.wait_group %0;" :: "n"(N) : "memory")

// ============================================================================
// GroupNorm fused with transpose+bf16: x fp32 [c][p] -> g_xnT bf16 [p][c]
// ============================================================================
__global__ __launch_bounds__(512) void gnT_kernel(const float* __restrict__ x,
                                                  const float* __restrict__ w,
                                                  const float* __restrict__ bgn) {
    int bg = blockIdx.x;
    int b = bg >> 3, g = bg & 7;
    size_t base = (size_t)(b*CHANNELS + g*GCH) * SPATIAL;
    const float4* x4 = (const float4*)(x + base);
    int tid = threadIdx.x;

    float s = 0.f, ss = 0.f;
    for (int i = tid; i < GCH*SPATIAL/4; i += 512) {
        float4 v = x4[i];
        s  += v.x + v.y + v.z + v.w;
        ss += v.x*v.x + v.y*v.y + v.z*v.z + v.w*v.w;
    }
    __shared__ float rs[512], rq[512];
    rs[tid] = s; rq[tid] = ss;
    __syncthreads();
    for (int o = 256; o > 0; o >>= 1) {
        if (tid < o) { rs[tid] += rs[tid+o]; rq[tid] += rq[tid+o]; }
        __syncthreads();
    }
    float mu  = rs[0] * (1.f/65536.f);
    float var = rq[0] * (1.f/65536.f) - mu*mu;
    float rstd = rsqrtf(var + 1e-5f);

    __shared__ float tile[GCH][33];
    int cl = tid >> 3, p4 = (tid & 7) * 4;      // load role
    float wc = w[g*GCH + cl] * rstd;
    float bc = bgn[g*GCH + cl] - mu*wc;
    int pw = tid >> 4, c4 = (tid & 15) * 4;     // store role

    for (int pt = 0; pt < 32; pt++) {
        int pB = pt * 32;
        float4 v = *(const float4*)&x[base + (size_t)cl*SPATIAL + pB + p4];
        tile[cl][p4    ] = v.x*wc + bc;
        tile[cl][p4 + 1] = v.y*wc + bc;
        tile[cl][p4 + 2] = v.z*wc + bc;
        tile[cl][p4 + 3] = v.w*wc + bc;
        __syncthreads();
        uint2 o;
        o.x = packbf(tile[c4  ][pw], tile[c4+1][pw]);
        o.y = packbf(tile[c4+2][pw], tile[c4+3][pw]);
        *(uint2*)&g_xnT[((size_t)b*SPATIAL + pB + pw)*CHANNELS + g*GCH + c4] = o;
        __syncthreads();
    }
}

// ============================================================================
// Weight/bias prep
// ============================================================================
__global__ __launch_bounds__(256) void wprep(const float* __restrict__ qw, const float* __restrict__ kw,
                                             const float* __restrict__ vw, const float* __restrict__ pw,
                                             const float* __restrict__ qb, const float* __restrict__ kb,
                                             const float* __restrict__ vb, const float* __restrict__ pb) {
    int g = blockIdx.x*256 + threadIdx.x;
    if (g < 4*131072) {
        int m = g >> 17, r = g & 131071;
        const float* src = m == 0 ? qw : m == 1 ? kw : m == 2 ? vw : pw;
        float sc = (m == 0) ? 0.125f : 1.f;
        float2 v = *(const float2*)&src[(size_t)r*2];
        ((uint32_t*)g_w[m])[r] = packbf(v.x*sc, v.y*sc);
    } else {
        int gb = g - 4*131072;
        if (gb < 2048) {
            int m = gb >> 9, o = gb & 511;
            const float* src = m == 0 ? qb : m == 1 ? kb : m == 2 ? vb : pb;
            g_b[m][o] = src[o] * ((m == 0) ? 0.125f : 1.f);
        }
    }
}

// ============================================================================
// Conv1x1 bf16 m16n8k16 + ldmatrix, Kt=64, double-buffered cp.async.
// Tile 128(o)x128(p). smem rows 72 halves (144 B).
// ============================================================================
#define CONV_SMEM (4*9216*2)   // 73728 B

__device__ __forceinline__ void conv_stage_bf(uint16_t* sA, uint16_t* sB,
                                              const uint16_t* W, const uint16_t* Xt,
                                              int k0, int tid) {
    #pragma unroll
    for (int q = 0; q < 4; q++) {
        int i = tid + q*256;
        int row = i >> 3, c = (i & 7) * 8;
        cp16b(&sA[row*72 + c], &W[(size_t)row*CHANNELS + k0 + c]);
    }
    #pragma unroll
    for (int q = 0; q < 4; q++) {
        int i = tid + q*256;
        int row = i >> 3, c = (i & 7) * 8;
        cp16b(&sB[row*72 + c], &Xt[(size_t)row*CHANNELS + k0 + c]);
    }
}

__device__ __forceinline__ void conv_core_bf(const uint16_t* __restrict__ W,
                                             const float* __restrict__ bias,
                                             const uint16_t* __restrict__ Xt,
                                             int mode,
                                             uint16_t* __restrict__ outT,
                                             uint16_t* __restrict__ outD,
                                             float* __restrict__ outF,
                                             const float* __restrict__ resid) {
    extern __shared__ __align__(16) uint16_t csm[];
    uint16_t* sA[2] = { csm, csm + 9216 };
    uint16_t* sB[2] = { csm + 18432, csm + 27648 };

    int tid = threadIdx.x, lane = tid & 31, wid = tid >> 5;
    int wy = wid & 3, wx = wid >> 2;
    int lq = lane >> 2, lr = lane & 3;

    uint32_t aoff = (lane & 15)*144 + (lane >> 4)*16;
    uint32_t boff = (lane & 7)*144 + ((lane >> 3) & 1)*16 + (lane >> 4)*1152;

    float acc[2][8][4];
    #pragma unroll
    for (int i = 0; i < 2; i++)
        #pragma unroll
        for (int j = 0; j < 8; j++)
            #pragma unroll
            for (int t = 0; t < 4; t++) acc[i][j][t] = 0.f;

    conv_stage_bf(sA[0], sB[0], W, Xt, 0, tid);
    CP_COMMIT();

    for (int it = 0; it < 8; it++) {
        int cur = it & 1;
        if (it < 7) {
            conv_stage_bf(sA[cur^1], sB[cur^1], W, Xt, (it+1)*64, tid);
            CP_COMMIT();
            CP_WAIT(1);
        } else {
            CP_WAIT(0);
        }
        __syncthreads();

        uint32_t sAa = (uint32_t)__cvta_generic_to_shared(sA[cur]);
        uint32_t sBa = (uint32_t)__cvta_generic_to_shared(sB[cur]);
        #pragma unroll
        for (int ks = 0; ks < 4; ks++) {
            uint32_t a[2][4], b[4][4];
            #pragma unroll
            for (int mi = 0; mi < 2; mi++)
                ldm4(a[mi], sAa + (wy*32 + mi*16)*144 + ks*32 + aoff);
            #pragma unroll
            for (int pp = 0; pp < 4; pp++)
                ldm4(b[pp], sBa + (wx*64 + pp*16)*144 + ks*32 + boff);
            #pragma unroll
            for (int mi = 0; mi < 2; mi++)
                #pragma unroll
                for (int pp = 0; pp < 4; pp++) {
                    mma16(acc[mi][2*pp],   a[mi], &b[pp][0]);
                    mma16(acc[mi][2*pp+1], a[mi], &b[pp][2]);
                }
        }
        __syncthreads();
    }

    if (mode == 2) {
        #pragma unroll
        for (int mi = 0; mi < 2; mi++) {
            int o0 = wy*32 + mi*16 + lq;
            float bi0 = bias[o0], bi8 = bias[o0+8];
            #pragma unroll
            for (int ni = 0; ni < 8; ni++) {
                int p = wx*64 + ni*8 + lr*2;
                size_t off0 = (size_t)o0*SPATIAL + p;
                size_t off8 = (size_t)(o0+8)*SPATIAL + p;
                float2 r0 = make_float2(acc[mi][ni][0] + bi0, acc[mi][ni][1] + bi0);
                float2 r8 = make_float2(acc[mi][ni][2] + bi8, acc[mi][ni][3] + bi8);
                float2 v0 = *(const float2*)&resid[off0];
                float2 v8 = *(const float2*)&resid[off8];
                r0.x += v0.x; r0.y += v0.y;
                r8.x += v8.x; r8.y += v8.y;
                *(float2*)&outF[off0] = r0;
                *(float2*)&outF[off8] = r8;
            }
        }
    } else if (mode == 1) {
        #pragma unroll
        for (int mi = 0; mi < 2; mi++) {
            int o0 = wy*32 + mi*16 + lq;
            float bi0 = bias[o0], bi8 = bias[o0+8];
            uint32_t* r0 = (uint32_t*)(outD + (size_t)o0*SPATIAL);
            uint32_t* r8 = (uint32_t*)(outD + (size_t)(o0+8)*SPATIAL);
            #pragma unroll
            for (int ni = 0; ni < 8; ni++) {
                int pc = wx*32 + ni*4 + lr;
                r0[pc] = packbf(acc[mi][ni][0] + bi0, acc[mi][ni][1] + bi0);
                r8[pc] = packbf(acc[mi][ni][2] + bi8, acc[mi][ni][3] + bi8);
            }
        }
    } else {
        uint16_t* Ts = csm;   // [128 p][136]
        #pragma unroll
        for (int mi = 0; mi < 2; mi++) {
            int o0 = wy*32 + mi*16 + lq;
            float bi0 = bias[o0], bi8 = bias[o0+8];
            #pragma unroll
            for (int ni = 0; ni < 8; ni++) {
                int p = wx*64 + ni*8 + lr*2;
                Ts[(p  )*136 + o0    ] = bf16u(acc[mi][ni][0] + bi0);
                Ts[(p+1)*136 + o0    ] = bf16u(acc[mi][ni][1] + bi0);
                Ts[(p  )*136 + o0 + 8] = bf16u(acc[mi][ni][2] + bi8);
                Ts[(p+1)*136 + o0 + 8] = bf16u(acc[mi][ni][3] + bi8);
            }
        }
        __syncthreads();
        #pragma unroll
        for (int q = 0; q < 8; q++) {
            int i = tid + q*256;
            int p = i >> 4, c = (i & 15) * 8;
            *(uint4*)&outT[(size_t)p*CHANNELS + c] = *(uint4*)&Ts[p*136 + c];
        }
    }
}

__global__ __launch_bounds__(256, 2) void conv_qkv_bf() {
    int b = blockIdx.z;
    int sel = blockIdx.y >> 2;
    int oB = (blockIdx.y & 3) * 128;
    int pB = blockIdx.x * 128;
    const uint16_t* W = g_w[sel] + (size_t)oB*CHANNELS;
    const float* bias = g_b[sel] + oB;
    const uint16_t* Xt = g_xnT + ((size_t)b*SPATIAL + pB)*CHANNELS;
    if (sel == 2) {
        conv_core_bf(W, bias, Xt, 1, nullptr,
                     g_v + (size_t)b*BC + (size_t)oB*SPATIAL + pB, nullptr, nullptr);
    } else {
        uint16_t* gT = (sel == 0) ? g_qT : g_kT;
        conv_core_bf(W, bias, Xt, 0,
                     gT + (size_t)b*BC + (size_t)pB*CHANNELS + oB,
                     nullptr, nullptr, nullptr);
    }
}

__global__ __launch_bounds__(256, 2) void conv_proj_bf(const float* __restrict__ x,
                                                       float* __restrict__ out) {
    int b = blockIdx.z, oB = blockIdx.y*128, pB = blockIdx.x*128;
    conv_core_bf(g_w[3] + (size_t)oB*CHANNELS, g_b[3] + oB,
                 g_aoT + ((size_t)b*SPATIAL + pB)*CHANNELS, 2,
                 nullptr, nullptr,
                 out + (size_t)b*BC + (size_t)oB*SPATIAL + pB,
                 x + (size_t)b*BC + (size_t)oB*SPATIAL + pB);
}

// ============================================================================
// Flash bf16, m-tile 128, 8 iterations, double-buffered K/V.
// smem halves: Q[128][72] | K0[128][72] | K1 | V0[64][136] | V1
// ============================================================================
#define FQ  0
#define FK0 9216
#define FK1 18432
#define FV0 27648
#define FV1 36352
#define FL_SMEM (45056 * 2)   // 90112 B

__global__ __launch_bounds__(256, 2) void flash_bf() {
    extern __shared__ __align__(16) uint16_t fsm[];
    int nB = blockIdx.x * 128;
    int bh = blockIdx.y;
    int b = bh >> 3, h = bh & 7;
    const uint16_t* qT = g_qT + (size_t)b*BC + h*HDIM;
    const uint16_t* kT = g_kT + (size_t)b*BC + h*HDIM;
    const uint16_t* vB = g_v  + (size_t)b*BC + (size_t)h*HDIM*SPATIAL;
    uint16_t* aoT      = g_aoT + (size_t)b*BC + h*HDIM;

    int tid = threadIdx.x, lane = tid & 31, wid = tid >> 5;
    int lq = lane >> 2, lr = lane & 3;
    int n0 = wid * 16;

    uint32_t aoff  = (lane & 15)*144 + (lane >> 4)*16;
    uint32_t boff  = (lane & 7)*144 + ((lane >> 3) & 1)*16 + (lane >> 4)*1152;
    uint32_t vboff = (lane & 7)*272 + ((lane >> 3) & 1)*16 + (lane >> 4)*2176;

    // stage Q [n128][d64]
    #pragma unroll
    for (int q = 0; q < 4; q++) {
        int i = tid + q*256;
        int row = i >> 3, c = (i & 7) * 8;
        cp16b(&fsm[FQ + row*72 + c], &qT[(size_t)(nB + row)*CHANNELS + c]);
    }
    // stage K [m128][d64], V [d64][m128] tile 0
    #pragma unroll
    for (int q = 0; q < 4; q++) {
        int i = tid + q*256;
        int row = i >> 3, c = (i & 7) * 8;
        cp16b(&fsm[FK0 + row*72 + c], &kT[(size_t)row*CHANNELS + c]);
        int vr = i >> 4, vc = (i & 15) * 8;
        cp16b(&fsm[FV0 + vr*136 + vc], &vB[(size_t)vr*SPATIAL + vc]);
    }
    CP_COMMIT();

    float accO[8][4];
    #pragma unroll
    for (int i = 0; i < 8; i++)
        #pragma unroll
        for (int t = 0; t < 4; t++) accO[i][t] = 0.f;
    float mPrev0 = -1e30f, mPrev8 = -1e30f;
    float l0 = 0.f, l8 = 0.f;

    uint32_t Qa = (uint32_t)__cvta_generic_to_shared(fsm + FQ) + n0*144 + aoff;

    for (int it = 0; it < 8; it++) {
        int cur = it & 1;
        if (it < 7) {
            int m1 = (it+1)*128;
            uint16_t* Kn = fsm + (cur ? FK0 : FK1);
            uint16_t* Vn = fsm + (cur ? FV0 : FV1);
            #pragma unroll
            for (int q = 0; q < 4; q++) {
                int i = tid + q*256;
                int row = i >> 3, c = (i & 7) * 8;
                cp16b(&Kn[row*72 + c], &kT[(size_t)(m1 + row)*CHANNELS + c]);
                int vr = i >> 4, vc = (i & 15) * 8;
                cp16b(&Vn[vr*136 + vc], &vB[(size_t)vr*SPATIAL + m1 + vc]);
            }
            CP_COMMIT();
            CP_WAIT(1);
        } else {
            CP_WAIT(0);
        }
        __syncthreads();

        uint32_t Ka = (uint32_t)__cvta_generic_to_shared(fsm + (cur ? FK1 : FK0)) + boff;
        uint32_t Va = (uint32_t)__cvta_generic_to_shared(fsm + (cur ? FV1 : FV0)) + vboff;

        // ---- S = Q K^T : 16 rows x 128 keys ----
        float accS[16][4];
        #pragma unroll
        for (int i = 0; i < 16; i++)
            #pragma unroll
            for (int t = 0; t < 4; t++) accS[i][t] = 0.f;
        #pragma unroll
        for (int ks = 0; ks < 4; ks++) {
            uint32_t a[4];
            ldm4(a, Qa + ks*32);
            #pragma unroll
            for (int pp = 0; pp < 8; pp++) {
                uint32_t bb[4];
                ldm4(bb, Ka + pp*2304 + ks*32);
                mma16(accS[2*pp],   a, &bb[0]);
                mma16(accS[2*pp+1], a, &bb[2]);
            }
        }

        // ---- online softmax ----
        float tm0 = -1e30f, tm8 = -1e30f;
        #pragma unroll
        for (int ni = 0; ni < 16; ni++) {
            tm0 = fmaxf(tm0, fmaxf(accS[ni][0], accS[ni][1]));
            tm8 = fmaxf(tm8, fmaxf(accS[ni][2], accS[ni][3]));
        }
        tm0 = fmaxf(tm0, __shfl_xor_sync(0xffffffffu, tm0, 1));
        tm0 = fmaxf(tm0, __shfl_xor_sync(0xffffffffu, tm0, 2));
        tm8 = fmaxf(tm8, __shfl_xor_sync(0xffffffffu, tm8, 1));
        tm8 = fmaxf(tm8, __shfl_xor_sync(0xffffffffu, tm8, 2));

        float mNew0 = fmaxf(mPrev0, tm0);
        float mNew8 = fmaxf(mPrev8, tm8);
        float alpha0 = __expf(mPrev0 - mNew0);
        float alpha8 = __expf(mPrev8 - mNew8);
        mPrev0 = mNew0; mPrev8 = mNew8;

        uint32_t pk0[16], pk8[16];
        float sum0 = 0.f, sum8 = 0.f;
        #pragma unroll
        for (int ni = 0; ni < 16; ni++) {
            float p0 = __expf(accS[ni][0] - mNew0);
            float p1 = __expf(accS[ni][1] - mNew0);
            float p2 = __expf(accS[ni][2] - mNew8);
            float p3 = __expf(accS[ni][3] - mNew8);
            sum0 += p0 + p1; sum8 += p2 + p3;
            pk0[ni] = packbf(p0, p1);
            pk8[ni] = packbf(p2, p3);
        }
        sum0 += __shfl_xor_sync(0xffffffffu, sum0, 1);
        sum0 += __shfl_xor_sync(0xffffffffu, sum0, 2);
        sum8 += __shfl_xor_sync(0xffffffffu, sum8, 1);
        sum8 += __shfl_xor_sync(0xffffffffu, sum8, 2);
        l0 = l0*alpha0 + sum0;
        l8 = l8*alpha8 + sum8;

        #pragma unroll
        for (int ni = 0; ni < 8; ni++) {
            accO[ni][0] *= alpha0; accO[ni][1] *= alpha0;
            accO[ni][2] *= alpha8; accO[ni][3] *= alpha8;
        }

        // ---- O += P V^T ----
        #pragma unroll
        for (int ks = 0; ks < 8; ks++) {
            uint32_t a[4] = { pk0[2*ks], pk8[2*ks], pk0[2*ks+1], pk8[2*ks+1] };
            #pragma unroll
            for (int pp = 0; pp < 4; pp++) {
                uint32_t bb[4];
                ldm4(bb, Va + pp*4352 + ks*32);
                mma16(accO[2*pp],   a, &bb[0]);
                mma16(accO[2*pp+1], a, &bb[2]);
            }
        }
        __syncthreads();
    }

    // ---- finalize: bf16 store to aoT [p][c] ----
    float inv0 = 1.f / l0, inv8 = 1.f / l8;
    uint32_t* r0 = (uint32_t*)(aoT + (size_t)(nB + n0 + lq)*CHANNELS);
    uint32_t* r8 = (uint32_t*)(aoT + (size_t)(nB + n0 + lq + 8)*CHANNELS);
    #pragma unroll
    for (int ni = 0; ni < 8; ni++) {
        r0[ni*4 + lr] = packbf(accO[ni][0]*inv0, accO[ni][1]*inv0);
        r8[ni*4 + lr] = packbf(accO[ni][2]*inv8, accO[ni][3]*inv8);
    }
}

// ============================================================================
extern "C" void kernel_launch(void* const* d_in, const int* in_sizes, int n_in,
                              void* d_out, int out_size) {
    const float* x  = (const float*)d_in[0];
    const float* nw = (const float*)d_in[1];
    const float* nb = (const float*)d_in[2];
    const float* qw = (const float*)d_in[3];
    const float* qb = (const float*)d_in[4];
    const float* kw = (const float*)d_in[5];
    const float* kb = (const float*)d_in[6];
    const float* vw = (const float*)d_in[7];
    const float* vb = (const float*)d_in[8];
    const float* pw = (const float*)d_in[9];
    const float* pb = (const float*)d_in[10];
    float* out = (float*)d_out;
    (void)in_sizes; (void)n_in; (void)out_size;

    cudaFuncSetAttribute(flash_bf,
                         cudaFuncAttributeMaxDynamicSharedMemorySize, (int)FL_SMEM);
    cudaFuncSetAttribute(conv_qkv_bf,
                         cudaFuncAttributeMaxDynamicSharedMemorySize, (int)CONV_SMEM);
    cudaFuncSetAttribute(conv_proj_bf,
                         cudaFuncAttributeMaxDynamicSharedMemorySize, (int)CONV_SMEM);

    wprep<<<2056, 256>>>(qw, kw, vw, pw, qb, kb, vb, pb);
    gnT_kernel<<<BATCH*8, 512>>>(x, nw, nb);

    conv_qkv_bf<<<dim3(SPATIAL/128, 12, BATCH), 256, CONV_SMEM>>>();

    flash_bf<<<dim3(SPATIAL/128, NBH), 256, FL_SMEM>>>();

    conv_proj_bf<<<dim3(SPATIAL/128, CHANNELS/128, BATCH), 256, CONV_SMEM>>>(x, out);
}